// round 12
// baseline (speedup 1.0000x reference)
#include <cuda_runtime.h>
#include <cuda_fp16.h>
#include <math.h>

#define FULL_MASK 0xFFFFFFFFu

#define MAXN 200000
#define MAXE 6400000
#define MAXG 4096
#define NB2 2048     // persistent gather/stats blocks

// ---- scratch: static device globals, referenced DIRECTLY by kernels ----
__device__ __align__(16) int    g_deg[MAXN];
__device__ __align__(16) int    g_rowptr[MAXN + 1];
__device__ __align__(16) int    g_cursor[MAXN];
__device__ __align__(16) int    g_bsum[1024];
__device__ __align__(16) int    g_src32[MAXE];
__device__ __align__(16) int    g_dst32[MAXE];
__device__ __align__(16) int2   g_csr_ent[MAXE];      // {src, norm bits}
__device__ __align__(16) float  g_dinv[MAXN];
__device__ __align__(16) __half g_bufA[MAXN * 32];    // fp16 gather input
__device__ __align__(16) float  g_bufB[MAXN * 32];    // fp32 gather output
__device__ __align__(16) float  g_part[NB2 * 64];     // per-block [sum(32)|sumsq(32)]
__device__ __align__(16) float  g_scale[32];
__device__ __align__(16) float  g_shift[32];
__device__ __align__(16) float  g_gsum[MAXG];
__device__ __align__(16) float  g_gcnt[MAXG];
__device__ int g_is64;   // 1 if integer inputs are int64 on device, else int32

__device__ __forceinline__ int load_idx(const void* p, size_t i) {
    if (g_is64) return (int)(((const long long*)p)[i]);
    return ((const int*)p)[i];
}
__device__ __forceinline__ int clampi(int v, int lo, int hi) {
    return v < lo ? lo : (v > hi ? hi : v);
}
__device__ __forceinline__ uint2 pack4h(float a, float b, float c, float d) {
    __half2 h0 = __float22half2_rn(make_float2(a, b));
    __half2 h1 = __float22half2_rn(make_float2(c, d));
    uint2 u;
    u.x = *reinterpret_cast<unsigned*>(&h0);
    u.y = *reinterpret_cast<unsigned*>(&h1);
    return u;
}

// ---------------------------------------------------------------------------
// 0a) dtype detection: int64 values < 2^31 have zero odd 32-bit words.
// ---------------------------------------------------------------------------
__global__ void detect_kernel(const int* __restrict__ ei_words, int nwords) {
    if (threadIdx.x == 0 && blockIdx.x == 0) {
        int acc = 0;
        for (int i = 1; i < 32 && i < nwords; i += 2) acc |= ei_words[i];
        g_is64 = (acc == 0) ? 1 : 0;
    }
}

// 0b) zero init (deg histogram + pool accumulators)
__global__ void zero_init_kernel(int N, int G) {
    int i = blockIdx.x * blockDim.x + threadIdx.x;
    int stride = gridDim.x * blockDim.x;
    for (int k = i; k < N; k += stride) g_deg[k] = 0;
    for (int k = i; k < G; k += stride) { g_gsum[k] = 0.0f; g_gcnt[k] = 0.0f; }
}

// ---------------------------------------------------------------------------
// 1) decode edges to int32 + degree histogram over dst
// ---------------------------------------------------------------------------
__global__ void prep_kernel(const void* __restrict__ ei, int E, int N) {
    int e = blockIdx.x * blockDim.x + threadIdx.x;
    if (e >= E) return;
    int s = clampi(load_idx(ei, e), 0, N - 1);
    int d = clampi(load_idx(ei, (size_t)E + e), 0, N - 1);
    g_src32[e] = s;
    g_dst32[e] = d;
    atomicAdd(&g_deg[d], 1);
}

__global__ void dinv_kernel(int N) {
    int i = blockIdx.x * blockDim.x + threadIdx.x;
    if (i < N) g_dinv[i] = rsqrtf((float)g_deg[i] + 1.0f);
}

// ---------------------------------------------------------------------------
// 2) exclusive scan of deg -> rowptr (3-kernel block scan); cursor = rowptr
// ---------------------------------------------------------------------------
__global__ void scan_blocksum(int N) {
    __shared__ int s[1024];
    int tid = threadIdx.x;
    int i = blockIdx.x * 1024 + tid;
    s[tid] = (i < N) ? g_deg[i] : 0;
    __syncthreads();
#pragma unroll
    for (int o = 512; o; o >>= 1) {
        if (tid < o) s[tid] += s[tid + o];
        __syncthreads();
    }
    if (tid == 0) g_bsum[blockIdx.x] = s[0];
}

__global__ void scan_bsums(int nb) {
    __shared__ int s[1024];
    int tid = threadIdx.x;
    s[tid] = (tid < nb) ? g_bsum[tid] : 0;
    __syncthreads();
#pragma unroll
    for (int o = 1; o < 1024; o <<= 1) {
        int t = (tid >= o) ? s[tid - o] : 0;
        __syncthreads();
        s[tid] += t;
        __syncthreads();
    }
    if (tid < nb) g_bsum[tid] = (tid == 0) ? 0 : s[tid - 1];
}

__global__ void scan_write(int N, int E) {
    __shared__ int s[1024];
    int tid = threadIdx.x;
    int i = blockIdx.x * 1024 + tid;
    int v = (i < N) ? g_deg[i] : 0;
    s[tid] = v;
    __syncthreads();
#pragma unroll
    for (int o = 1; o < 1024; o <<= 1) {
        int t = (tid >= o) ? s[tid - o] : 0;
        __syncthreads();
        s[tid] += t;
        __syncthreads();
    }
    int excl = s[tid] - v + g_bsum[blockIdx.x];
    if (i < N) { g_rowptr[i] = excl; g_cursor[i] = excl; }
    if (i == N - 1) g_rowptr[N] = E;
}

// ---------------------------------------------------------------------------
// 3) CSR fill by dst: packed {src, norm} entries (reads decoded int32 edges)
// ---------------------------------------------------------------------------
__global__ void fill_kernel(int E) {
    int e = blockIdx.x * blockDim.x + threadIdx.x;
    if (e >= E) return;
    int s = g_src32[e];
    int d = g_dst32[e];
    int pos = atomicAdd(&g_cursor[d], 1);
    if (pos >= 0 && pos < E) {
        float w = g_dinv[s] * g_dinv[d];
        g_csr_ent[pos] = make_int2(s, __float_as_int(w));
    }
}

// ---------------------------------------------------------------------------
// 4) GEMM layer 1:  bufA[n,j] = sum_k x[n,k] * W[k,j]   (K=128, J=32), fp16 out
// ---------------------------------------------------------------------------
__global__ void gemm1_kernel(const float* __restrict__ x, const float* __restrict__ W, int N) {
    __shared__ float Ws[128 * 32];
    __shared__ float Xs[32 * 132];
    int tid = threadIdx.x;  // 128

    for (int i = tid; i < 128 * 32; i += 128) Ws[i] = W[i];

    int n0 = blockIdx.x * 32;
    int rem = N - n0; if (rem > 32) rem = 32;
    for (int idx = tid; idx < rem * 32; idx += 128) {
        int node = idx >> 5, k4 = idx & 31;
        float4 v = *(const float4*)(x + (size_t)(n0 + node) * 128 + k4 * 4);
        float* dp = Xs + node * 132 + 4 * k4;
        dp[0] = v.x; dp[1] = v.y; dp[2] = v.z; dp[3] = v.w;
    }
    __syncthreads();

    int c = tid & 7;   // col group
    int r = tid >> 3;  // node pair
    float acc[2][4];
#pragma unroll
    for (int i = 0; i < 2; i++)
#pragma unroll
        for (int j = 0; j < 4; j++) acc[i][j] = 0.0f;

#pragma unroll 8
    for (int k = 0; k < 128; k++) {
        float4 w = *(const float4*)(Ws + k * 32 + c * 4);
#pragma unroll
        for (int i = 0; i < 2; i++) {
            float xv = Xs[(r * 2 + i) * 132 + k];
            acc[i][0] += xv * w.x;
            acc[i][1] += xv * w.y;
            acc[i][2] += xv * w.z;
            acc[i][3] += xv * w.w;
        }
    }
    uint2* outA = (uint2*)g_bufA;
#pragma unroll
    for (int i = 0; i < 2; i++) {
        int n = n0 + r * 2 + i;
        if (n < N)
            outA[(size_t)n * 8 + c] = pack4h(acc[i][0], acc[i][1], acc[i][2], acc[i][3]);
    }
}

// ---------------------------------------------------------------------------
// 5) GEMM layers 2/3, BN folded into X load:  bufA(fp16) = BN(bufB) @ W
// ---------------------------------------------------------------------------
__global__ void gemm_bn_kernel(const float* __restrict__ W, int N) {
    __shared__ float Ws[32 * 32];
    __shared__ float Xs[64 * 36];
    __shared__ float sc[32], sh[32];
    int tid = threadIdx.x;  // 128

    for (int i = tid; i < 1024; i += 128) Ws[i] = W[i];
    if (tid < 32) { sc[tid] = g_scale[tid]; sh[tid] = g_shift[tid]; }
    __syncthreads();

    int n0 = blockIdx.x * 64;
    for (int idx = tid; idx < 64 * 8; idx += 128) {
        int node = idx >> 3, k4 = idx & 7;
        int n = n0 + node;
        float4 v = (n < N) ? *(const float4*)(g_bufB + (size_t)n * 32 + k4 * 4)
                           : make_float4(0, 0, 0, 0);
        int k = 4 * k4;
        float* dp = Xs + node * 36 + k;
        dp[0] = v.x * sc[k + 0] + sh[k + 0];
        dp[1] = v.y * sc[k + 1] + sh[k + 1];
        dp[2] = v.z * sc[k + 2] + sh[k + 2];
        dp[3] = v.w * sc[k + 3] + sh[k + 3];
    }
    __syncthreads();

    int c = tid & 7, r = tid >> 3;
    float acc[4][4];
#pragma unroll
    for (int i = 0; i < 4; i++)
#pragma unroll
        for (int j = 0; j < 4; j++) acc[i][j] = 0.0f;

#pragma unroll
    for (int k = 0; k < 32; k++) {
        float4 w = *(const float4*)(Ws + k * 32 + c * 4);
#pragma unroll
        for (int i = 0; i < 4; i++) {
            float xv = Xs[(r * 4 + i) * 36 + k];
            acc[i][0] += xv * w.x;
            acc[i][1] += xv * w.y;
            acc[i][2] += xv * w.z;
            acc[i][3] += xv * w.w;
        }
    }
    uint2* outA = (uint2*)g_bufA;
#pragma unroll
    for (int i = 0; i < 4; i++) {
        int n = n0 + r * 4 + i;
        if (n < N)
            outA[(size_t)n * 8 + c] = pack4h(acc[i][0], acc[i][1], acc[i][2], acc[i][3]);
    }
}

// ---------------------------------------------------------------------------
// Core gather body (fp16 input): warp per node; octet = edge slot, sub = 4-feature
// group (uint2 = 4 halves). Returns reduced acc (valid on octet 0 lanes).
// ---------------------------------------------------------------------------
__device__ __forceinline__ float4 gather_node(const uint2* __restrict__ hin, int v) {
    int lane = threadIdx.x & 31;
    int octet = lane >> 3, sub = lane & 7;
    int beg = g_rowptr[v], end = g_rowptr[v + 1];
    float4 acc = make_float4(0.f, 0.f, 0.f, 0.f);
    if (octet == 0) {
        float di = g_dinv[v];
        float d2 = di * di;
        uint2 u = hin[(size_t)v * 8 + sub];
        float2 f0 = __half22float2(*reinterpret_cast<__half2*>(&u.x));
        float2 f1 = __half22float2(*reinterpret_cast<__half2*>(&u.y));
        acc.x = d2 * f0.x; acc.y = d2 * f0.y; acc.z = d2 * f1.x; acc.w = d2 * f1.y;
    }
    for (int base = beg; base < end; base += 8) {
        int i1 = base + octet, i2 = base + 4 + octet;
        int s1 = v, s2 = v;
        float w1 = 0.f, w2 = 0.f;
        if (i1 < end) { int2 e1 = g_csr_ent[i1]; s1 = e1.x; w1 = __int_as_float(e1.y); }
        if (i2 < end) { int2 e2 = g_csr_ent[i2]; s2 = e2.x; w2 = __int_as_float(e2.y); }
        uint2 u1 = hin[(size_t)s1 * 8 + sub];
        uint2 u2 = hin[(size_t)s2 * 8 + sub];
        float2 a0 = __half22float2(*reinterpret_cast<__half2*>(&u1.x));
        float2 a1 = __half22float2(*reinterpret_cast<__half2*>(&u1.y));
        float2 b0 = __half22float2(*reinterpret_cast<__half2*>(&u2.x));
        float2 b1 = __half22float2(*reinterpret_cast<__half2*>(&u2.y));
        acc.x += w1 * a0.x + w2 * b0.x;
        acc.y += w1 * a0.y + w2 * b0.y;
        acc.z += w1 * a1.x + w2 * b1.x;
        acc.w += w1 * a1.y + w2 * b1.y;
    }
#pragma unroll
    for (int off = 8; off <= 16; off <<= 1) {
        acc.x += __shfl_xor_sync(FULL_MASK, acc.x, off);
        acc.y += __shfl_xor_sync(FULL_MASK, acc.y, off);
        acc.z += __shfl_xor_sync(FULL_MASK, acc.z, off);
        acc.w += __shfl_xor_sync(FULL_MASK, acc.w, off);
    }
    return acc;
}

// ---------------------------------------------------------------------------
// 6) Gather + tanh + bias + BN partial stats (layers 1, 2). Persistent grid NB2.
// ---------------------------------------------------------------------------
__global__ void gather_stats_kernel(const float* __restrict__ bias, int N) {
    int tid = threadIdx.x, warp = tid >> 5, lane = tid & 31;
    int octet = lane >> 3, sub = lane & 7;
    const uint2* hin = (const uint2*)g_bufA;
    float4* hout = (float4*)g_bufB;
    float4 b4 = ((const float4*)bias)[sub];
    float4 s4 = make_float4(0.f, 0.f, 0.f, 0.f);
    float4 q4 = make_float4(0.f, 0.f, 0.f, 0.f);

    int warpId = blockIdx.x * 8 + warp;
    int nwarp = gridDim.x * 8;
    for (int v = warpId; v < N; v += nwarp) {
        float4 acc = gather_node(hin, v);
        if (octet == 0) {
            float4 t;
            t.x = tanhf(acc.x + b4.x);
            t.y = tanhf(acc.y + b4.y);
            t.z = tanhf(acc.z + b4.z);
            t.w = tanhf(acc.w + b4.w);
            hout[(size_t)v * 8 + sub] = t;
            s4.x += t.x; s4.y += t.y; s4.z += t.z; s4.w += t.w;
            q4.x += t.x * t.x; q4.y += t.y * t.y; q4.z += t.z * t.z; q4.w += t.w * t.w;
        }
    }
    __shared__ float ss[8][32], sq[8][32];
    if (octet == 0) {
        ss[warp][sub * 4 + 0] = s4.x; ss[warp][sub * 4 + 1] = s4.y;
        ss[warp][sub * 4 + 2] = s4.z; ss[warp][sub * 4 + 3] = s4.w;
        sq[warp][sub * 4 + 0] = q4.x; sq[warp][sub * 4 + 1] = q4.y;
        sq[warp][sub * 4 + 2] = q4.z; sq[warp][sub * 4 + 3] = q4.w;
    }
    __syncthreads();
    if (tid < 64) {
        float acc = 0.f;
        if (tid < 32) {
#pragma unroll
            for (int w = 0; w < 8; w++) acc += ss[w][tid];
        } else {
#pragma unroll
            for (int w = 0; w < 8; w++) acc += sq[w][tid - 32];
        }
        g_part[blockIdx.x * 64 + tid] = acc;
    }
}

// deterministic reduce of NB2 partials; scale/shift for folded BN
__global__ void finalize_kernel(const float* __restrict__ g, const float* __restrict__ be,
                                double invN) {
    __shared__ float red[4][64];
    int tid = threadIdx.x;           // 256 threads
    int j = tid & 63, c = tid >> 6;  // feature, chunk
    float acc = 0.f;
    for (int b = c; b < NB2; b += 4) acc += g_part[b * 64 + j];
    red[c][j] = acc;
    __syncthreads();
    if (tid < 32) {
        float S = red[0][tid] + red[1][tid] + red[2][tid] + red[3][tid];
        float Q = red[0][tid + 32] + red[1][tid + 32] + red[2][tid + 32] + red[3][tid + 32];
        float mu  = (float)((double)S * invN);
        float ex2 = (float)((double)Q * invN);
        float var = ex2 - mu * mu;
        float s = g[tid] * rsqrtf(var + 1e-5f);
        g_scale[tid] = s;
        g_shift[tid] = be[tid] - mu * s;
    }
}

// ---------------------------------------------------------------------------
// 7) Gather + tanh + pool head (layer 3): t = tanh(agg + b3) . Wc -> graph sums
// ---------------------------------------------------------------------------
__global__ void gather_pool_kernel(const float* __restrict__ b3, const float* __restrict__ Wc,
                                   const void* __restrict__ batch, int N, int G) {
    int tid = threadIdx.x, warp = tid >> 5, lane = tid & 31;
    int octet = lane >> 3, sub = lane & 7;
    const uint2* hin = (const uint2*)g_bufA;
    float4 b4 = ((const float4*)b3)[sub];
    float4 wc4 = ((const float4*)Wc)[sub];

    int warpId = blockIdx.x * 8 + warp;
    int nwarp = gridDim.x * 8;
    for (int v = warpId; v < N; v += nwarp) {
        float4 acc = gather_node(hin, v);
        if (octet == 0) {
            float t = tanhf(acc.x + b4.x) * wc4.x
                    + tanhf(acc.y + b4.y) * wc4.y
                    + tanhf(acc.z + b4.z) * wc4.z
                    + tanhf(acc.w + b4.w) * wc4.w;
#pragma unroll
            for (int off = 4; off; off >>= 1) t += __shfl_xor_sync(0x000000FFu, t, off);
            if (sub == 0) {
                int gid = clampi(load_idx(batch, v), 0, G - 1);
                atomicAdd(&g_gsum[gid], t);
                atomicAdd(&g_gcnt[gid], 1.0f);
            }
        }
    }
}

__global__ void out_kernel(const float* __restrict__ bc, float* __restrict__ out, int G) {
    int g = blockIdx.x * blockDim.x + threadIdx.x;
    if (g < G) out[g] = g_gsum[g] / fmaxf(g_gcnt[g], 1.0f) + bc[0];
}

// ---------------------------------------------------------------------------
extern "C" void kernel_launch(void* const* d_in, const int* in_sizes, int n_in,
                              void* d_out, int out_size) {
    const float* x     = (const float*)d_in[0];
    const void*  ei    = d_in[1];
    const void*  batch = d_in[2];
    const float* W1 = (const float*)d_in[3];  const float* b1 = (const float*)d_in[4];
    const float* g1 = (const float*)d_in[5];  const float* be1 = (const float*)d_in[6];
    const float* W2 = (const float*)d_in[7];  const float* b2 = (const float*)d_in[8];
    const float* g2 = (const float*)d_in[9];  const float* be2 = (const float*)d_in[10];
    const float* W3 = (const float*)d_in[11]; const float* b3 = (const float*)d_in[12];
    // d_in[13], d_in[14] (g3/be3) unused: the reference has no BN after layer 3
    const float* Wc = (const float*)d_in[15]; const float* bc = (const float*)d_in[16];
    float* out = (float*)d_out;

    int N = in_sizes[0] / 128;
    int E = in_sizes[1] / 2;
    int G = out_size;

    int eb = (E + 255) / 256;
    int nb = (N + 1023) / 1024;
    int g1Blocks = (N + 31) / 32;
    int gbBlocks = (N + 63) / 64;
    double invN = 1.0 / (double)N;

    // side stream + events for overlapping gemm1 with the CSR build chain.
    // Created once (outside capture, on the correctness call); reused thereafter.
    static cudaStream_t s2 = 0;
    static cudaEvent_t evFork = 0, evJoin = 0;
    if (!s2) {
        if (cudaStreamCreateWithFlags(&s2, cudaStreamNonBlocking) != cudaSuccess) s2 = 0;
        if (s2) {
            cudaEventCreateWithFlags(&evFork, cudaEventDisableTiming);
            cudaEventCreateWithFlags(&evJoin, cudaEventDisableTiming);
        }
    }

    // ---- init (stream 0) ----
    detect_kernel<<<1, 32>>>((const int*)ei, 2 * E);
    zero_init_kernel<<<256, 256>>>(N, G);

    // ---- fork: gemm1 on s2, CSR build on stream 0 ----
    if (s2) {
        cudaEventRecord(evFork, 0);
        cudaStreamWaitEvent(s2, evFork, 0);
        gemm1_kernel<<<g1Blocks, 128, 0, s2>>>(x, W1, N);
        cudaEventRecord(evJoin, s2);
    } else {
        gemm1_kernel<<<g1Blocks, 128>>>(x, W1, N);
    }

    prep_kernel<<<eb, 256>>>(ei, E, N);
    dinv_kernel<<<(N + 255) / 256, 256>>>(N);
    scan_blocksum<<<nb, 1024>>>(N);
    scan_bsums<<<1, 1024>>>(nb);
    scan_write<<<nb, 1024>>>(N, E);
    fill_kernel<<<eb, 256>>>(E);

    if (s2) cudaStreamWaitEvent(0, evJoin, 0);

    // ---- layer 1 ----
    gather_stats_kernel<<<NB2, 256>>>(b1, N);
    finalize_kernel<<<1, 256>>>(g1, be1, invN);

    // ---- layer 2 ----
    gemm_bn_kernel<<<gbBlocks, 128>>>(W2, N);
    gather_stats_kernel<<<NB2, 256>>>(b2, N);
    finalize_kernel<<<1, 256>>>(g2, be2, invN);

    // ---- layer 3 ----
    gemm_bn_kernel<<<gbBlocks, 128>>>(W3, N);
    gather_pool_kernel<<<NB2, 256>>>(b3, Wc, batch, N, G);

    // ---- head ----
    out_kernel<<<(G + 255) / 256, 256>>>(bc, out, G);
}

// round 13
// speedup vs baseline: 1.0113x; 1.0113x over previous
#include <cuda_runtime.h>
#include <cuda_fp16.h>
#include <math.h>

#define FULL_MASK 0xFFFFFFFFu

#define MAXN 200000
#define MAXE 6400000
#define MAXG 4096
#define NB2 2048     // persistent gather/stats blocks

// ---- scratch: static device globals, referenced DIRECTLY by kernels ----
__device__ __align__(16) int    g_deg[MAXN];
__device__ __align__(16) int    g_rowptr[MAXN + 1];
__device__ __align__(16) int    g_cursor[MAXN];
__device__ __align__(16) int    g_bsum[1024];
__device__ __align__(16) int    g_src32[MAXE];
__device__ __align__(16) int    g_dst32[MAXE];
__device__ __align__(16) int2   g_csr_ent[MAXE];      // {src, norm bits}
__device__ __align__(16) float  g_dinv[MAXN];
__device__ __align__(16) __half g_bufA[MAXN * 32];    // fp16 gather input
__device__ __align__(16) float  g_bufB[MAXN * 32];    // fp32 gather output
__device__ __align__(16) float  g_part[NB2 * 64];     // per-block [sum(32)|sumsq(32)]
__device__ __align__(16) float  g_scale[32];
__device__ __align__(16) float  g_shift[32];
__device__ __align__(16) float  g_gsum[MAXG];
__device__ __align__(16) float  g_gcnt[MAXG];
__device__ int g_is64;   // 1 if integer inputs are int64 on device, else int32

__device__ __forceinline__ int load_idx(const void* p, size_t i) {
    if (g_is64) return (int)(((const long long*)p)[i]);
    return ((const int*)p)[i];
}
__device__ __forceinline__ int clampi(int v, int lo, int hi) {
    return v < lo ? lo : (v > hi ? hi : v);
}
__device__ __forceinline__ uint2 pack4h(float a, float b, float c, float d) {
    __half2 h0 = __float22half2_rn(make_float2(a, b));
    __half2 h1 = __float22half2_rn(make_float2(c, d));
    uint2 u;
    u.x = *reinterpret_cast<unsigned*>(&h0);
    u.y = *reinterpret_cast<unsigned*>(&h1);
    return u;
}

// ---------------------------------------------------------------------------
// 0a) dtype detection: int64 values < 2^31 have zero odd 32-bit words.
// ---------------------------------------------------------------------------
__global__ void detect_kernel(const int* __restrict__ ei_words, int nwords) {
    if (threadIdx.x == 0 && blockIdx.x == 0) {
        int acc = 0;
        for (int i = 1; i < 32 && i < nwords; i += 2) acc |= ei_words[i];
        g_is64 = (acc == 0) ? 1 : 0;
    }
}

// 0b) zero init (deg histogram + pool accumulators)
__global__ void zero_init_kernel(int N, int G) {
    int i = blockIdx.x * blockDim.x + threadIdx.x;
    int stride = gridDim.x * blockDim.x;
    for (int k = i; k < N; k += stride) g_deg[k] = 0;
    for (int k = i; k < G; k += stride) { g_gsum[k] = 0.0f; g_gcnt[k] = 0.0f; }
}

// ---------------------------------------------------------------------------
// 1) decode edges to int32 + degree histogram over dst
// ---------------------------------------------------------------------------
__global__ void prep_kernel(const void* __restrict__ ei, int E, int N) {
    int e = blockIdx.x * blockDim.x + threadIdx.x;
    if (e >= E) return;
    int s = clampi(load_idx(ei, e), 0, N - 1);
    int d = clampi(load_idx(ei, (size_t)E + e), 0, N - 1);
    g_src32[e] = s;
    g_dst32[e] = d;
    atomicAdd(&g_deg[d], 1);
}

__global__ void dinv_kernel(int N) {
    int i = blockIdx.x * blockDim.x + threadIdx.x;
    if (i < N) g_dinv[i] = rsqrtf((float)g_deg[i] + 1.0f);
}

// ---------------------------------------------------------------------------
// 2) exclusive scan of deg -> rowptr (3-kernel block scan); cursor = rowptr
// ---------------------------------------------------------------------------
__global__ void scan_blocksum(int N) {
    __shared__ int s[1024];
    int tid = threadIdx.x;
    int i = blockIdx.x * 1024 + tid;
    s[tid] = (i < N) ? g_deg[i] : 0;
    __syncthreads();
#pragma unroll
    for (int o = 512; o; o >>= 1) {
        if (tid < o) s[tid] += s[tid + o];
        __syncthreads();
    }
    if (tid == 0) g_bsum[blockIdx.x] = s[0];
}

__global__ void scan_bsums(int nb) {
    __shared__ int s[1024];
    int tid = threadIdx.x;
    s[tid] = (tid < nb) ? g_bsum[tid] : 0;
    __syncthreads();
#pragma unroll
    for (int o = 1; o < 1024; o <<= 1) {
        int t = (tid >= o) ? s[tid - o] : 0;
        __syncthreads();
        s[tid] += t;
        __syncthreads();
    }
    if (tid < nb) g_bsum[tid] = (tid == 0) ? 0 : s[tid - 1];
}

__global__ void scan_write(int N, int E) {
    __shared__ int s[1024];
    int tid = threadIdx.x;
    int i = blockIdx.x * 1024 + tid;
    int v = (i < N) ? g_deg[i] : 0;
    s[tid] = v;
    __syncthreads();
#pragma unroll
    for (int o = 1; o < 1024; o <<= 1) {
        int t = (tid >= o) ? s[tid - o] : 0;
        __syncthreads();
        s[tid] += t;
        __syncthreads();
    }
    int excl = s[tid] - v + g_bsum[blockIdx.x];
    if (i < N) { g_rowptr[i] = excl; g_cursor[i] = excl; }
    if (i == N - 1) g_rowptr[N] = E;
}

// ---------------------------------------------------------------------------
// 3) CSR fill by dst: packed {src, norm} entries (reads decoded int32 edges)
// ---------------------------------------------------------------------------
__global__ void fill_kernel(int E) {
    int e = blockIdx.x * blockDim.x + threadIdx.x;
    if (e >= E) return;
    int s = g_src32[e];
    int d = g_dst32[e];
    int pos = atomicAdd(&g_cursor[d], 1);
    if (pos >= 0 && pos < E) {
        float w = g_dinv[s] * g_dinv[d];
        g_csr_ent[pos] = make_int2(s, __float_as_int(w));
    }
}

// ---------------------------------------------------------------------------
// 4) GEMM layer 1:  bufA[n,j] = sum_k x[n,k] * W[k,j]   (K=128, J=32), fp16 out
// ---------------------------------------------------------------------------
__global__ void gemm1_kernel(const float* __restrict__ x, const float* __restrict__ W, int N) {
    __shared__ float Ws[128 * 32];
    __shared__ float Xs[32 * 132];
    int tid = threadIdx.x;  // 128

    for (int i = tid; i < 128 * 32; i += 128) Ws[i] = W[i];

    int n0 = blockIdx.x * 32;
    int rem = N - n0; if (rem > 32) rem = 32;
    for (int idx = tid; idx < rem * 32; idx += 128) {
        int node = idx >> 5, k4 = idx & 31;
        float4 v = *(const float4*)(x + (size_t)(n0 + node) * 128 + k4 * 4);
        float* dp = Xs + node * 132 + 4 * k4;
        dp[0] = v.x; dp[1] = v.y; dp[2] = v.z; dp[3] = v.w;
    }
    __syncthreads();

    int c = tid & 7;   // col group
    int r = tid >> 3;  // node pair
    float acc[2][4];
#pragma unroll
    for (int i = 0; i < 2; i++)
#pragma unroll
        for (int j = 0; j < 4; j++) acc[i][j] = 0.0f;

#pragma unroll 8
    for (int k = 0; k < 128; k++) {
        float4 w = *(const float4*)(Ws + k * 32 + c * 4);
#pragma unroll
        for (int i = 0; i < 2; i++) {
            float xv = Xs[(r * 2 + i) * 132 + k];
            acc[i][0] += xv * w.x;
            acc[i][1] += xv * w.y;
            acc[i][2] += xv * w.z;
            acc[i][3] += xv * w.w;
        }
    }
    uint2* outA = (uint2*)g_bufA;
#pragma unroll
    for (int i = 0; i < 2; i++) {
        int n = n0 + r * 2 + i;
        if (n < N)
            outA[(size_t)n * 8 + c] = pack4h(acc[i][0], acc[i][1], acc[i][2], acc[i][3]);
    }
}

// ---------------------------------------------------------------------------
// 5) GEMM layers 2/3, BN folded into X load:  bufA(fp16) = BN(bufB) @ W
// ---------------------------------------------------------------------------
__global__ void gemm_bn_kernel(const float* __restrict__ W, int N) {
    __shared__ float Ws[32 * 32];
    __shared__ float Xs[64 * 36];
    __shared__ float sc[32], sh[32];
    int tid = threadIdx.x;  // 128

    for (int i = tid; i < 1024; i += 128) Ws[i] = W[i];
    if (tid < 32) { sc[tid] = g_scale[tid]; sh[tid] = g_shift[tid]; }
    __syncthreads();

    int n0 = blockIdx.x * 64;
    for (int idx = tid; idx < 64 * 8; idx += 128) {
        int node = idx >> 3, k4 = idx & 7;
        int n = n0 + node;
        float4 v = (n < N) ? *(const float4*)(g_bufB + (size_t)n * 32 + k4 * 4)
                           : make_float4(0, 0, 0, 0);
        int k = 4 * k4;
        float* dp = Xs + node * 36 + k;
        dp[0] = v.x * sc[k + 0] + sh[k + 0];
        dp[1] = v.y * sc[k + 1] + sh[k + 1];
        dp[2] = v.z * sc[k + 2] + sh[k + 2];
        dp[3] = v.w * sc[k + 3] + sh[k + 3];
    }
    __syncthreads();

    int c = tid & 7, r = tid >> 3;
    float acc[4][4];
#pragma unroll
    for (int i = 0; i < 4; i++)
#pragma unroll
        for (int j = 0; j < 4; j++) acc[i][j] = 0.0f;

#pragma unroll
    for (int k = 0; k < 32; k++) {
        float4 w = *(const float4*)(Ws + k * 32 + c * 4);
#pragma unroll
        for (int i = 0; i < 4; i++) {
            float xv = Xs[(r * 4 + i) * 36 + k];
            acc[i][0] += xv * w.x;
            acc[i][1] += xv * w.y;
            acc[i][2] += xv * w.z;
            acc[i][3] += xv * w.w;
        }
    }
    uint2* outA = (uint2*)g_bufA;
#pragma unroll
    for (int i = 0; i < 4; i++) {
        int n = n0 + r * 4 + i;
        if (n < N)
            outA[(size_t)n * 8 + c] = pack4h(acc[i][0], acc[i][1], acc[i][2], acc[i][3]);
    }
}

// ---------------------------------------------------------------------------
// Core gather body (fp16 input): warp per node; octet = edge slot, sub = 4-feature
// group (uint2 = 4 halves). Returns reduced acc (valid on octet 0 lanes).
// ---------------------------------------------------------------------------
__device__ __forceinline__ float4 gather_node(const uint2* __restrict__ hin, int v) {
    int lane = threadIdx.x & 31;
    int octet = lane >> 3, sub = lane & 7;
    int beg = g_rowptr[v], end = g_rowptr[v + 1];
    float4 acc = make_float4(0.f, 0.f, 0.f, 0.f);
    if (octet == 0) {
        float di = g_dinv[v];
        float d2 = di * di;
        uint2 u = hin[(size_t)v * 8 + sub];
        float2 f0 = __half22float2(*reinterpret_cast<__half2*>(&u.x));
        float2 f1 = __half22float2(*reinterpret_cast<__half2*>(&u.y));
        acc.x = d2 * f0.x; acc.y = d2 * f0.y; acc.z = d2 * f1.x; acc.w = d2 * f1.y;
    }
    for (int base = beg; base < end; base += 8) {
        int i1 = base + octet, i2 = base + 4 + octet;
        int s1 = v, s2 = v;
        float w1 = 0.f, w2 = 0.f;
        if (i1 < end) { int2 e1 = g_csr_ent[i1]; s1 = e1.x; w1 = __int_as_float(e1.y); }
        if (i2 < end) { int2 e2 = g_csr_ent[i2]; s2 = e2.x; w2 = __int_as_float(e2.y); }
        uint2 u1 = hin[(size_t)s1 * 8 + sub];
        uint2 u2 = hin[(size_t)s2 * 8 + sub];
        float2 a0 = __half22float2(*reinterpret_cast<__half2*>(&u1.x));
        float2 a1 = __half22float2(*reinterpret_cast<__half2*>(&u1.y));
        float2 b0 = __half22float2(*reinterpret_cast<__half2*>(&u2.x));
        float2 b1 = __half22float2(*reinterpret_cast<__half2*>(&u2.y));
        acc.x += w1 * a0.x + w2 * b0.x;
        acc.y += w1 * a0.y + w2 * b0.y;
        acc.z += w1 * a1.x + w2 * b1.x;
        acc.w += w1 * a1.y + w2 * b1.y;
    }
#pragma unroll
    for (int off = 8; off <= 16; off <<= 1) {
        acc.x += __shfl_xor_sync(FULL_MASK, acc.x, off);
        acc.y += __shfl_xor_sync(FULL_MASK, acc.y, off);
        acc.z += __shfl_xor_sync(FULL_MASK, acc.z, off);
        acc.w += __shfl_xor_sync(FULL_MASK, acc.w, off);
    }
    return acc;
}

// ---------------------------------------------------------------------------
// 6) Gather + tanh + bias + BN partial stats (layers 1, 2). Persistent grid NB2.
// ---------------------------------------------------------------------------
__global__ void gather_stats_kernel(const float* __restrict__ bias, int N) {
    int tid = threadIdx.x, warp = tid >> 5, lane = tid & 31;
    int octet = lane >> 3, sub = lane & 7;
    const uint2* hin = (const uint2*)g_bufA;
    float4* hout = (float4*)g_bufB;
    float4 b4 = ((const float4*)bias)[sub];
    float4 s4 = make_float4(0.f, 0.f, 0.f, 0.f);
    float4 q4 = make_float4(0.f, 0.f, 0.f, 0.f);

    int warpId = blockIdx.x * 8 + warp;
    int nwarp = gridDim.x * 8;
    for (int v = warpId; v < N; v += nwarp) {
        float4 acc = gather_node(hin, v);
        if (octet == 0) {
            float4 t;
            t.x = tanhf(acc.x + b4.x);
            t.y = tanhf(acc.y + b4.y);
            t.z = tanhf(acc.z + b4.z);
            t.w = tanhf(acc.w + b4.w);
            hout[(size_t)v * 8 + sub] = t;
            s4.x += t.x; s4.y += t.y; s4.z += t.z; s4.w += t.w;
            q4.x += t.x * t.x; q4.y += t.y * t.y; q4.z += t.z * t.z; q4.w += t.w * t.w;
        }
    }
    __shared__ float ss[8][32], sq[8][32];
    if (octet == 0) {
        ss[warp][sub * 4 + 0] = s4.x; ss[warp][sub * 4 + 1] = s4.y;
        ss[warp][sub * 4 + 2] = s4.z; ss[warp][sub * 4 + 3] = s4.w;
        sq[warp][sub * 4 + 0] = q4.x; sq[warp][sub * 4 + 1] = q4.y;
        sq[warp][sub * 4 + 2] = q4.z; sq[warp][sub * 4 + 3] = q4.w;
    }
    __syncthreads();
    if (tid < 64) {
        float acc = 0.f;
        if (tid < 32) {
#pragma unroll
            for (int w = 0; w < 8; w++) acc += ss[w][tid];
        } else {
#pragma unroll
            for (int w = 0; w < 8; w++) acc += sq[w][tid - 32];
        }
        g_part[blockIdx.x * 64 + tid] = acc;
    }
}

// deterministic reduce of NB2 partials; scale/shift for folded BN
__global__ void finalize_kernel(const float* __restrict__ g, const float* __restrict__ be,
                                double invN) {
    __shared__ float red[4][64];
    int tid = threadIdx.x;           // 256 threads
    int j = tid & 63, c = tid >> 6;  // feature, chunk
    float acc = 0.f;
    for (int b = c; b < NB2; b += 4) acc += g_part[b * 64 + j];
    red[c][j] = acc;
    __syncthreads();
    if (tid < 32) {
        float S = red[0][tid] + red[1][tid] + red[2][tid] + red[3][tid];
        float Q = red[0][tid + 32] + red[1][tid + 32] + red[2][tid + 32] + red[3][tid + 32];
        float mu  = (float)((double)S * invN);
        float ex2 = (float)((double)Q * invN);
        float var = ex2 - mu * mu;
        float s = g[tid] * rsqrtf(var + 1e-5f);
        g_scale[tid] = s;
        g_shift[tid] = be[tid] - mu * s;
    }
}

// ---------------------------------------------------------------------------
// 7) Gather + tanh + pool head (layer 3): t = tanh(agg + b3) . Wc -> graph sums
// ---------------------------------------------------------------------------
__global__ void gather_pool_kernel(const float* __restrict__ b3, const float* __restrict__ Wc,
                                   const void* __restrict__ batch, int N, int G) {
    int tid = threadIdx.x, warp = tid >> 5, lane = tid & 31;
    int octet = lane >> 3, sub = lane & 7;
    const uint2* hin = (const uint2*)g_bufA;
    float4 b4 = ((const float4*)b3)[sub];
    float4 wc4 = ((const float4*)Wc)[sub];

    int warpId = blockIdx.x * 8 + warp;
    int nwarp = gridDim.x * 8;
    for (int v = warpId; v < N; v += nwarp) {
        float4 acc = gather_node(hin, v);
        if (octet == 0) {
            float t = tanhf(acc.x + b4.x) * wc4.x
                    + tanhf(acc.y + b4.y) * wc4.y
                    + tanhf(acc.z + b4.z) * wc4.z
                    + tanhf(acc.w + b4.w) * wc4.w;
#pragma unroll
            for (int off = 4; off; off >>= 1) t += __shfl_xor_sync(0x000000FFu, t, off);
            if (sub == 0) {
                int gid = clampi(load_idx(batch, v), 0, G - 1);
                atomicAdd(&g_gsum[gid], t);
                atomicAdd(&g_gcnt[gid], 1.0f);
            }
        }
    }
}

__global__ void out_kernel(const float* __restrict__ bc, float* __restrict__ out, int G) {
    int g = blockIdx.x * blockDim.x + threadIdx.x;
    if (g < G) out[g] = g_gsum[g] / fmaxf(g_gcnt[g], 1.0f) + bc[0];
}

// ---------------------------------------------------------------------------
extern "C" void kernel_launch(void* const* d_in, const int* in_sizes, int n_in,
                              void* d_out, int out_size) {
    const float* x     = (const float*)d_in[0];
    const void*  ei    = d_in[1];
    const void*  batch = d_in[2];
    const float* W1 = (const float*)d_in[3];  const float* b1 = (const float*)d_in[4];
    const float* g1 = (const float*)d_in[5];  const float* be1 = (const float*)d_in[6];
    const float* W2 = (const float*)d_in[7];  const float* b2 = (const float*)d_in[8];
    const float* g2 = (const float*)d_in[9];  const float* be2 = (const float*)d_in[10];
    const float* W3 = (const float*)d_in[11]; const float* b3 = (const float*)d_in[12];
    // d_in[13], d_in[14] (g3/be3) unused: the reference has no BN after layer 3
    const float* Wc = (const float*)d_in[15]; const float* bc = (const float*)d_in[16];
    float* out = (float*)d_out;

    int N = in_sizes[0] / 128;
    int E = in_sizes[1] / 2;
    int G = out_size;

    int eb = (E + 255) / 256;
    int nb = (N + 1023) / 1024;
    int g1Blocks = (N + 31) / 32;
    int gbBlocks = (N + 63) / 64;
    double invN = 1.0 / (double)N;

    // side stream + events for overlapping gemm1 with the CSR build chain.
    // Created once (outside capture, on the correctness call); reused thereafter.
    static cudaStream_t s2 = 0;
    static cudaEvent_t evFork = 0, evJoin = 0;
    if (!s2) {
        if (cudaStreamCreateWithFlags(&s2, cudaStreamNonBlocking) != cudaSuccess) s2 = 0;
        if (s2) {
            cudaEventCreateWithFlags(&evFork, cudaEventDisableTiming);
            cudaEventCreateWithFlags(&evJoin, cudaEventDisableTiming);
        }
    }

    // ---- init (stream 0) ----
    detect_kernel<<<1, 32>>>((const int*)ei, 2 * E);
    zero_init_kernel<<<256, 256>>>(N, G);

    // ---- fork: gemm1 on s2, CSR build on stream 0 ----
    if (s2) {
        cudaEventRecord(evFork, 0);
        cudaStreamWaitEvent(s2, evFork, 0);
        gemm1_kernel<<<g1Blocks, 128, 0, s2>>>(x, W1, N);
        cudaEventRecord(evJoin, s2);
    } else {
        gemm1_kernel<<<g1Blocks, 128>>>(x, W1, N);
    }

    prep_kernel<<<eb, 256>>>(ei, E, N);
    dinv_kernel<<<(N + 255) / 256, 256>>>(N);
    scan_blocksum<<<nb, 1024>>>(N);
    scan_bsums<<<1, 1024>>>(nb);
    scan_write<<<nb, 1024>>>(N, E);
    fill_kernel<<<eb, 256>>>(E);

    if (s2) cudaStreamWaitEvent(0, evJoin, 0);

    // ---- layer 1 ----
    gather_stats_kernel<<<NB2, 256>>>(b1, N);
    finalize_kernel<<<1, 256>>>(g1, be1, invN);

    // ---- layer 2 ----
    gemm_bn_kernel<<<gbBlocks, 128>>>(W2, N);
    gather_stats_kernel<<<NB2, 256>>>(b2, N);
    finalize_kernel<<<1, 256>>>(g2, be2, invN);

    // ---- layer 3 ----
    gemm_bn_kernel<<<gbBlocks, 128>>>(W3, N);
    gather_pool_kernel<<<NB2, 256>>>(b3, Wc, batch, N, G);

    // ---- head ----
    out_kernel<<<(G + 255) / 256, 256>>>(bc, out, G);
}

// round 14
// speedup vs baseline: 1.1201x; 1.1076x over previous
#include <cuda_runtime.h>
#include <cuda_fp16.h>
#include <math.h>

#define FULL_MASK 0xFFFFFFFFu

#define MAXN 200000
#define MAXE 6400000
#define MAXG 4096
#define NB2 2048     // persistent gather/stats blocks

// ---- scratch: static device globals, referenced DIRECTLY by kernels ----
__device__ __align__(16) int    g_deg[MAXN];
__device__ __align__(16) int    g_rowptr[MAXN + 1];
__device__ __align__(16) int    g_cursor[MAXN];
__device__ __align__(16) int    g_bsum[1024];
__device__ __align__(16) int    g_src32[MAXE];
__device__ __align__(16) int    g_dst32[MAXE];
__device__ __align__(16) int2   g_csr_ent[MAXE];      // {src, norm bits}
__device__ __align__(16) float  g_dinv[MAXN];
__device__ __align__(16) __half g_bufA[MAXN * 32];    // fp16 gather input
__device__ __align__(16) float  g_bufB[MAXN * 32];    // fp32 gather output
__device__ __align__(16) float  g_part[NB2 * 64];     // per-block [sum(32)|sumsq(32)]
__device__ __align__(16) float  g_scale[32];
__device__ __align__(16) float  g_shift[32];
__device__ __align__(16) float  g_gsum[MAXG];
__device__ __align__(16) float  g_gcnt[MAXG];
__device__ int g_is64;   // 1 if integer inputs are int64 on device, else int32

__device__ __forceinline__ int load_idx(const void* p, size_t i) {
    if (g_is64) return (int)(((const long long*)p)[i]);
    return ((const int*)p)[i];
}
__device__ __forceinline__ int clampi(int v, int lo, int hi) {
    return v < lo ? lo : (v > hi ? hi : v);
}
__device__ __forceinline__ uint2 pack4h(float a, float b, float c, float d) {
    __half2 h0 = __float22half2_rn(make_float2(a, b));
    __half2 h1 = __float22half2_rn(make_float2(c, d));
    uint2 u;
    u.x = *reinterpret_cast<unsigned*>(&h0);
    u.y = *reinterpret_cast<unsigned*>(&h1);
    return u;
}

// ---------------------------------------------------------------------------
// 0a) dtype detection: int64 values < 2^31 have zero odd 32-bit words.
// ---------------------------------------------------------------------------
__global__ void detect_kernel(const int* __restrict__ ei_words, int nwords) {
    if (threadIdx.x == 0 && blockIdx.x == 0) {
        int acc = 0;
        for (int i = 1; i < 32 && i < nwords; i += 2) acc |= ei_words[i];
        g_is64 = (acc == 0) ? 1 : 0;
    }
}

// 0b) zero init (deg histogram + pool accumulators)
__global__ void zero_init_kernel(int N, int G) {
    int i = blockIdx.x * blockDim.x + threadIdx.x;
    int stride = gridDim.x * blockDim.x;
    for (int k = i; k < N; k += stride) g_deg[k] = 0;
    for (int k = i; k < G; k += stride) { g_gsum[k] = 0.0f; g_gcnt[k] = 0.0f; }
}

// ---------------------------------------------------------------------------
// 1) decode edges to int32 + degree histogram over dst
// ---------------------------------------------------------------------------
__global__ void prep_kernel(const void* __restrict__ ei, int E, int N) {
    int e = blockIdx.x * blockDim.x + threadIdx.x;
    if (e >= E) return;
    int s = clampi(load_idx(ei, e), 0, N - 1);
    int d = clampi(load_idx(ei, (size_t)E + e), 0, N - 1);
    g_src32[e] = s;
    g_dst32[e] = d;
    atomicAdd(&g_deg[d], 1);
}

// ---------------------------------------------------------------------------
// 2) exclusive scan of deg -> rowptr (3-kernel block scan); cursor = rowptr
//    dinv computed inside scan_write (saves a pass + launch)
// ---------------------------------------------------------------------------
__global__ void scan_blocksum(int N) {
    __shared__ int s[1024];
    int tid = threadIdx.x;
    int i = blockIdx.x * 1024 + tid;
    s[tid] = (i < N) ? g_deg[i] : 0;
    __syncthreads();
#pragma unroll
    for (int o = 512; o; o >>= 1) {
        if (tid < o) s[tid] += s[tid + o];
        __syncthreads();
    }
    if (tid == 0) g_bsum[blockIdx.x] = s[0];
}

__global__ void scan_bsums(int nb) {
    __shared__ int s[1024];
    int tid = threadIdx.x;
    s[tid] = (tid < nb) ? g_bsum[tid] : 0;
    __syncthreads();
#pragma unroll
    for (int o = 1; o < 1024; o <<= 1) {
        int t = (tid >= o) ? s[tid - o] : 0;
        __syncthreads();
        s[tid] += t;
        __syncthreads();
    }
    if (tid < nb) g_bsum[tid] = (tid == 0) ? 0 : s[tid - 1];
}

__global__ void scan_write(int N, int E) {
    __shared__ int s[1024];
    int tid = threadIdx.x;
    int i = blockIdx.x * 1024 + tid;
    int v = (i < N) ? g_deg[i] : 0;
    s[tid] = v;
    __syncthreads();
#pragma unroll
    for (int o = 1; o < 1024; o <<= 1) {
        int t = (tid >= o) ? s[tid - o] : 0;
        __syncthreads();
        s[tid] += t;
        __syncthreads();
    }
    int excl = s[tid] - v + g_bsum[blockIdx.x];
    if (i < N) {
        g_rowptr[i] = excl;
        g_cursor[i] = excl;
        g_dinv[i] = rsqrtf((float)v + 1.0f);
    }
    if (i == N - 1) g_rowptr[N] = E;
}

// ---------------------------------------------------------------------------
// 3) CSR fill by dst: packed {src, norm} entries (reads decoded int32 edges)
// ---------------------------------------------------------------------------
__global__ void fill_kernel(int E) {
    int e = blockIdx.x * blockDim.x + threadIdx.x;
    if (e >= E) return;
    int s = g_src32[e];
    int d = g_dst32[e];
    int pos = atomicAdd(&g_cursor[d], 1);
    if (pos >= 0 && pos < E) {
        float w = g_dinv[s] * g_dinv[d];
        g_csr_ent[pos] = make_int2(s, __float_as_int(w));
    }
}

// ---------------------------------------------------------------------------
// 4) GEMM layer 1:  bufA[n,j] = sum_k x[n,k] * W[k,j]   (K=128, J=32), fp16 out
// ---------------------------------------------------------------------------
__global__ void gemm1_kernel(const float* __restrict__ x, const float* __restrict__ W, int N) {
    __shared__ float Ws[128 * 32];
    __shared__ float Xs[32 * 132];
    int tid = threadIdx.x;  // 128

    for (int i = tid; i < 128 * 32; i += 128) Ws[i] = W[i];

    int n0 = blockIdx.x * 32;
    int rem = N - n0; if (rem > 32) rem = 32;
    for (int idx = tid; idx < rem * 32; idx += 128) {
        int node = idx >> 5, k4 = idx & 31;
        float4 v = *(const float4*)(x + (size_t)(n0 + node) * 128 + k4 * 4);
        float* dp = Xs + node * 132 + 4 * k4;
        dp[0] = v.x; dp[1] = v.y; dp[2] = v.z; dp[3] = v.w;
    }
    __syncthreads();

    int c = tid & 7;   // col group
    int r = tid >> 3;  // node pair
    float acc[2][4];
#pragma unroll
    for (int i = 0; i < 2; i++)
#pragma unroll
        for (int j = 0; j < 4; j++) acc[i][j] = 0.0f;

#pragma unroll 8
    for (int k = 0; k < 128; k++) {
        float4 w = *(const float4*)(Ws + k * 32 + c * 4);
#pragma unroll
        for (int i = 0; i < 2; i++) {
            float xv = Xs[(r * 2 + i) * 132 + k];
            acc[i][0] += xv * w.x;
            acc[i][1] += xv * w.y;
            acc[i][2] += xv * w.z;
            acc[i][3] += xv * w.w;
        }
    }
    uint2* outA = (uint2*)g_bufA;
#pragma unroll
    for (int i = 0; i < 2; i++) {
        int n = n0 + r * 2 + i;
        if (n < N)
            outA[(size_t)n * 8 + c] = pack4h(acc[i][0], acc[i][1], acc[i][2], acc[i][3]);
    }
}

// ---------------------------------------------------------------------------
// 5) GEMM layers 2/3, BN folded into X load:  bufA(fp16) = BN(bufB) @ W
// ---------------------------------------------------------------------------
__global__ void gemm_bn_kernel(const float* __restrict__ W, int N) {
    __shared__ float Ws[32 * 32];
    __shared__ float Xs[64 * 36];
    __shared__ float sc[32], sh[32];
    int tid = threadIdx.x;  // 128

    for (int i = tid; i < 1024; i += 128) Ws[i] = W[i];
    if (tid < 32) { sc[tid] = g_scale[tid]; sh[tid] = g_shift[tid]; }
    __syncthreads();

    int n0 = blockIdx.x * 64;
    for (int idx = tid; idx < 64 * 8; idx += 128) {
        int node = idx >> 3, k4 = idx & 7;
        int n = n0 + node;
        float4 v = (n < N) ? *(const float4*)(g_bufB + (size_t)n * 32 + k4 * 4)
                           : make_float4(0, 0, 0, 0);
        int k = 4 * k4;
        float* dp = Xs + node * 36 + k;
        dp[0] = v.x * sc[k + 0] + sh[k + 0];
        dp[1] = v.y * sc[k + 1] + sh[k + 1];
        dp[2] = v.z * sc[k + 2] + sh[k + 2];
        dp[3] = v.w * sc[k + 3] + sh[k + 3];
    }
    __syncthreads();

    int c = tid & 7, r = tid >> 3;
    float acc[4][4];
#pragma unroll
    for (int i = 0; i < 4; i++)
#pragma unroll
        for (int j = 0; j < 4; j++) acc[i][j] = 0.0f;

#pragma unroll
    for (int k = 0; k < 32; k++) {
        float4 w = *(const float4*)(Ws + k * 32 + c * 4);
#pragma unroll
        for (int i = 0; i < 4; i++) {
            float xv = Xs[(r * 4 + i) * 36 + k];
            acc[i][0] += xv * w.x;
            acc[i][1] += xv * w.y;
            acc[i][2] += xv * w.z;
            acc[i][3] += xv * w.w;
        }
    }
    uint2* outA = (uint2*)g_bufA;
#pragma unroll
    for (int i = 0; i < 4; i++) {
        int n = n0 + r * 4 + i;
        if (n < N)
            outA[(size_t)n * 8 + c] = pack4h(acc[i][0], acc[i][1], acc[i][2], acc[i][3]);
    }
}

// ---------------------------------------------------------------------------
// Core gather body (fp16, software-pipelined, 16 edges/iter):
// warp per node; octet (lane>>3) picks 1 of 4 edge slots per group-of-4,
// sub (lane&7) = 4-feature group. Entries for the NEXT iteration are
// prefetched while this iteration's feature loads are in flight, so the
// entry->feature address-dependency chain is pre-resolved.
// Out-of-range slots use sentinel {src=0, w=0} (reads node 0, adds 0).
// ---------------------------------------------------------------------------
__device__ __forceinline__ float4 gather_node(const uint2* __restrict__ hin, int v) {
    int lane = threadIdx.x & 31;
    int octet = lane >> 3, sub = lane & 7;
    int beg = g_rowptr[v], end = g_rowptr[v + 1];
    const uint2* hs = hin + sub;
    float4 acc = make_float4(0.f, 0.f, 0.f, 0.f);
    if (octet == 0) {
        float di = g_dinv[v];
        float d2 = di * di;
        uint2 u = hs[(size_t)v * 8];
        float2 f0 = __half22float2(*reinterpret_cast<__half2*>(&u.x));
        float2 f1 = __half22float2(*reinterpret_cast<__half2*>(&u.y));
        acc.x = d2 * f0.x; acc.y = d2 * f0.y; acc.z = d2 * f1.x; acc.w = d2 * f1.y;
    }

    int2 e0, e1, e2, e3;
    {
        int i0 = beg + octet, i1 = beg + 4 + octet, i2 = beg + 8 + octet, i3 = beg + 12 + octet;
        e0 = (i0 < end) ? g_csr_ent[i0] : make_int2(0, 0);
        e1 = (i1 < end) ? g_csr_ent[i1] : make_int2(0, 0);
        e2 = (i2 < end) ? g_csr_ent[i2] : make_int2(0, 0);
        e3 = (i3 < end) ? g_csr_ent[i3] : make_int2(0, 0);
    }
    for (int base = beg; base < end; base += 16) {
        // prefetch next iteration's entries
        int nb = base + 16;
        int2 p0 = make_int2(0, 0), p1 = make_int2(0, 0), p2 = make_int2(0, 0), p3 = make_int2(0, 0);
        if (nb < end) {
            int i0 = nb + octet, i1 = nb + 4 + octet, i2 = nb + 8 + octet, i3 = nb + 12 + octet;
            if (i0 < end) p0 = g_csr_ent[i0];
            if (i1 < end) p1 = g_csr_ent[i1];
            if (i2 < end) p2 = g_csr_ent[i2];
            if (i3 < end) p3 = g_csr_ent[i3];
        }
        // 4 independent feature loads (addresses ready from previous iteration)
        uint2 u0 = hs[(size_t)e0.x * 8];
        uint2 u1 = hs[(size_t)e1.x * 8];
        uint2 u2 = hs[(size_t)e2.x * 8];
        uint2 u3 = hs[(size_t)e3.x * 8];
        float w0 = __int_as_float(e0.y), w1 = __int_as_float(e1.y);
        float w2 = __int_as_float(e2.y), w3 = __int_as_float(e3.y);
        float2 a0 = __half22float2(*reinterpret_cast<__half2*>(&u0.x));
        float2 a1 = __half22float2(*reinterpret_cast<__half2*>(&u0.y));
        float2 b0 = __half22float2(*reinterpret_cast<__half2*>(&u1.x));
        float2 b1 = __half22float2(*reinterpret_cast<__half2*>(&u1.y));
        float2 c0 = __half22float2(*reinterpret_cast<__half2*>(&u2.x));
        float2 c1 = __half22float2(*reinterpret_cast<__half2*>(&u2.y));
        float2 d0 = __half22float2(*reinterpret_cast<__half2*>(&u3.x));
        float2 d1 = __half22float2(*reinterpret_cast<__half2*>(&u3.y));
        acc.x += w0 * a0.x + w1 * b0.x + w2 * c0.x + w3 * d0.x;
        acc.y += w0 * a0.y + w1 * b0.y + w2 * c0.y + w3 * d0.y;
        acc.z += w0 * a1.x + w1 * b1.x + w2 * c1.x + w3 * d1.x;
        acc.w += w0 * a1.y + w1 * b1.y + w2 * c1.y + w3 * d1.y;
        e0 = p0; e1 = p1; e2 = p2; e3 = p3;
    }
#pragma unroll
    for (int off = 8; off <= 16; off <<= 1) {
        acc.x += __shfl_xor_sync(FULL_MASK, acc.x, off);
        acc.y += __shfl_xor_sync(FULL_MASK, acc.y, off);
        acc.z += __shfl_xor_sync(FULL_MASK, acc.z, off);
        acc.w += __shfl_xor_sync(FULL_MASK, acc.w, off);
    }
    return acc;
}

// ---------------------------------------------------------------------------
// 6) Gather + tanh + bias + BN partial stats (layers 1, 2). Persistent grid NB2.
// ---------------------------------------------------------------------------
__global__ void gather_stats_kernel(const float* __restrict__ bias, int N) {
    int tid = threadIdx.x, warp = tid >> 5, lane = tid & 31;
    int octet = lane >> 3, sub = lane & 7;
    const uint2* hin = (const uint2*)g_bufA;
    float4* hout = (float4*)g_bufB;
    float4 b4 = ((const float4*)bias)[sub];
    float4 s4 = make_float4(0.f, 0.f, 0.f, 0.f);
    float4 q4 = make_float4(0.f, 0.f, 0.f, 0.f);

    int warpId = blockIdx.x * 8 + warp;
    int nwarp = gridDim.x * 8;
    for (int v = warpId; v < N; v += nwarp) {
        float4 acc = gather_node(hin, v);
        if (octet == 0) {
            float4 t;
            t.x = tanhf(acc.x + b4.x);
            t.y = tanhf(acc.y + b4.y);
            t.z = tanhf(acc.z + b4.z);
            t.w = tanhf(acc.w + b4.w);
            hout[(size_t)v * 8 + sub] = t;
            s4.x += t.x; s4.y += t.y; s4.z += t.z; s4.w += t.w;
            q4.x += t.x * t.x; q4.y += t.y * t.y; q4.z += t.z * t.z; q4.w += t.w * t.w;
        }
    }
    __shared__ float ss[8][32], sq[8][32];
    if (octet == 0) {
        ss[warp][sub * 4 + 0] = s4.x; ss[warp][sub * 4 + 1] = s4.y;
        ss[warp][sub * 4 + 2] = s4.z; ss[warp][sub * 4 + 3] = s4.w;
        sq[warp][sub * 4 + 0] = q4.x; sq[warp][sub * 4 + 1] = q4.y;
        sq[warp][sub * 4 + 2] = q4.z; sq[warp][sub * 4 + 3] = q4.w;
    }
    __syncthreads();
    if (tid < 64) {
        float acc = 0.f;
        if (tid < 32) {
#pragma unroll
            for (int w = 0; w < 8; w++) acc += ss[w][tid];
        } else {
#pragma unroll
            for (int w = 0; w < 8; w++) acc += sq[w][tid - 32];
        }
        g_part[blockIdx.x * 64 + tid] = acc;
    }
}

// deterministic reduce of NB2 partials; scale/shift for folded BN
__global__ void finalize_kernel(const float* __restrict__ g, const float* __restrict__ be,
                                double invN) {
    __shared__ float red[4][64];
    int tid = threadIdx.x;           // 256 threads
    int j = tid & 63, c = tid >> 6;  // feature, chunk
    float acc = 0.f;
    for (int b = c; b < NB2; b += 4) acc += g_part[b * 64 + j];
    red[c][j] = acc;
    __syncthreads();
    if (tid < 32) {
        float S = red[0][tid] + red[1][tid] + red[2][tid] + red[3][tid];
        float Q = red[0][tid + 32] + red[1][tid + 32] + red[2][tid + 32] + red[3][tid + 32];
        float mu  = (float)((double)S * invN);
        float ex2 = (float)((double)Q * invN);
        float var = ex2 - mu * mu;
        float s = g[tid] * rsqrtf(var + 1e-5f);
        g_scale[tid] = s;
        g_shift[tid] = be[tid] - mu * s;
    }
}

// ---------------------------------------------------------------------------
// 7) Gather + tanh + pool head (layer 3): t = tanh(agg + b3) . Wc -> graph sums
// ---------------------------------------------------------------------------
__global__ void gather_pool_kernel(const float* __restrict__ b3, const float* __restrict__ Wc,
                                   const void* __restrict__ batch, int N, int G) {
    int tid = threadIdx.x, warp = tid >> 5, lane = tid & 31;
    int octet = lane >> 3, sub = lane & 7;
    const uint2* hin = (const uint2*)g_bufA;
    float4 b4 = ((const float4*)b3)[sub];
    float4 wc4 = ((const float4*)Wc)[sub];

    int warpId = blockIdx.x * 8 + warp;
    int nwarp = gridDim.x * 8;
    for (int v = warpId; v < N; v += nwarp) {
        float4 acc = gather_node(hin, v);
        if (octet == 0) {
            float t = tanhf(acc.x + b4.x) * wc4.x
                    + tanhf(acc.y + b4.y) * wc4.y
                    + tanhf(acc.z + b4.z) * wc4.z
                    + tanhf(acc.w + b4.w) * wc4.w;
#pragma unroll
            for (int off = 4; off; off >>= 1) t += __shfl_xor_sync(0x000000FFu, t, off);
            if (sub == 0) {
                int gid = clampi(load_idx(batch, v), 0, G - 1);
                atomicAdd(&g_gsum[gid], t);
                atomicAdd(&g_gcnt[gid], 1.0f);
            }
        }
    }
}

__global__ void out_kernel(const float* __restrict__ bc, float* __restrict__ out, int G) {
    int g = blockIdx.x * blockDim.x + threadIdx.x;
    if (g < G) out[g] = g_gsum[g] / fmaxf(g_gcnt[g], 1.0f) + bc[0];
}

// ---------------------------------------------------------------------------
extern "C" void kernel_launch(void* const* d_in, const int* in_sizes, int n_in,
                              void* d_out, int out_size) {
    const float* x     = (const float*)d_in[0];
    const void*  ei    = d_in[1];
    const void*  batch = d_in[2];
    const float* W1 = (const float*)d_in[3];  const float* b1 = (const float*)d_in[4];
    const float* g1 = (const float*)d_in[5];  const float* be1 = (const float*)d_in[6];
    const float* W2 = (const float*)d_in[7];  const float* b2 = (const float*)d_in[8];
    const float* g2 = (const float*)d_in[9];  const float* be2 = (const float*)d_in[10];
    const float* W3 = (const float*)d_in[11]; const float* b3 = (const float*)d_in[12];
    // d_in[13], d_in[14] (g3/be3) unused: the reference has no BN after layer 3
    const float* Wc = (const float*)d_in[15]; const float* bc = (const float*)d_in[16];
    float* out = (float*)d_out;

    int N = in_sizes[0] / 128;
    int E = in_sizes[1] / 2;
    int G = out_size;

    int eb = (E + 255) / 256;
    int nb = (N + 1023) / 1024;
    int g1Blocks = (N + 31) / 32;
    int gbBlocks = (N + 63) / 64;
    double invN = 1.0 / (double)N;

    // side stream + events for overlapping gemm1 with the CSR build chain.
    static cudaStream_t s2 = 0;
    static cudaEvent_t evFork = 0, evJoin = 0;
    if (!s2) {
        if (cudaStreamCreateWithFlags(&s2, cudaStreamNonBlocking) != cudaSuccess) s2 = 0;
        if (s2) {
            cudaEventCreateWithFlags(&evFork, cudaEventDisableTiming);
            cudaEventCreateWithFlags(&evJoin, cudaEventDisableTiming);
        }
    }

    // ---- init (stream 0) ----
    detect_kernel<<<1, 32>>>((const int*)ei, 2 * E);
    zero_init_kernel<<<256, 256>>>(N, G);

    // ---- fork: gemm1 on s2, CSR build on stream 0 ----
    if (s2) {
        cudaEventRecord(evFork, 0);
        cudaStreamWaitEvent(s2, evFork, 0);
        gemm1_kernel<<<g1Blocks, 128, 0, s2>>>(x, W1, N);
        cudaEventRecord(evJoin, s2);
    } else {
        gemm1_kernel<<<g1Blocks, 128>>>(x, W1, N);
    }

    prep_kernel<<<eb, 256>>>(ei, E, N);
    scan_blocksum<<<nb, 1024>>>(N);
    scan_bsums<<<1, 1024>>>(nb);
    scan_write<<<nb, 1024>>>(N, E);
    fill_kernel<<<eb, 256>>>(E);

    if (s2) cudaStreamWaitEvent(0, evJoin, 0);

    // ---- layer 1 ----
    gather_stats_kernel<<<NB2, 256>>>(b1, N);
    finalize_kernel<<<1, 256>>>(g1, be1, invN);

    // ---- layer 2 ----
    gemm_bn_kernel<<<gbBlocks, 128>>>(W2, N);
    gather_stats_kernel<<<NB2, 256>>>(b2, N);
    finalize_kernel<<<1, 256>>>(g2, be2, invN);

    // ---- layer 3 ----
    gemm_bn_kernel<<<gbBlocks, 128>>>(W3, N);
    gather_pool_kernel<<<NB2, 256>>>(b3, Wc, batch, N, G);

    // ---- head ----
    out_kernel<<<(G + 255) / 256, 256>>>(bc, out, G);
}

// round 15
// speedup vs baseline: 1.1490x; 1.0259x over previous
#include <cuda_runtime.h>
#include <cuda_fp16.h>
#include <math.h>

#define FULL_MASK 0xFFFFFFFFu

#define MAXN 200000
#define MAXE 6400000
#define MAXG 4096
#define NB2 2048     // persistent gather/stats blocks

// ---- scratch: static device globals, referenced DIRECTLY by kernels ----
__device__ __align__(16) int    g_deg[MAXN];
__device__ __align__(16) int    g_rowptr[MAXN + 1];
__device__ __align__(16) int    g_cursor[MAXN];
__device__ __align__(16) int    g_bsum[1024];
__device__ __align__(16) int    g_src32[MAXE];
__device__ __align__(16) int    g_dst32[MAXE];
__device__ __align__(16) int2   g_csr_ent[MAXE];      // {src, norm bits}
__device__ __align__(16) float  g_dinv[MAXN];
__device__ __align__(16) __half g_bufA[MAXN * 32];    // fp16 gather input
__device__ __align__(16) float  g_bufB[MAXN * 32];    // fp32 gather output
__device__ __align__(16) float  g_part[NB2 * 64];     // per-block [sum(32)|sumsq(32)]
__device__ __align__(16) float  g_scale[32];
__device__ __align__(16) float  g_shift[32];
__device__ __align__(16) float  g_gsum[MAXG];
__device__ __align__(16) float  g_gcnt[MAXG];
__device__ int g_is64;   // 1 if integer inputs are int64 on device, else int32

__device__ __forceinline__ int load_idx(const void* p, size_t i) {
    if (g_is64) return (int)(((const long long*)p)[i]);
    return ((const int*)p)[i];
}
__device__ __forceinline__ int clampi(int v, int lo, int hi) {
    return v < lo ? lo : (v > hi ? hi : v);
}
__device__ __forceinline__ uint2 pack4h(float a, float b, float c, float d) {
    __half2 h0 = __float22half2_rn(make_float2(a, b));
    __half2 h1 = __float22half2_rn(make_float2(c, d));
    uint2 u;
    u.x = *reinterpret_cast<unsigned*>(&h0);
    u.y = *reinterpret_cast<unsigned*>(&h1);
    return u;
}

// ---------------------------------------------------------------------------
// 0a) dtype detection: int64 values < 2^31 have zero odd 32-bit words.
// ---------------------------------------------------------------------------
__global__ void detect_kernel(const int* __restrict__ ei_words, int nwords) {
    if (threadIdx.x == 0 && blockIdx.x == 0) {
        int acc = 0;
        for (int i = 1; i < 32 && i < nwords; i += 2) acc |= ei_words[i];
        g_is64 = (acc == 0) ? 1 : 0;
    }
}

// 0b) zero init (deg histogram + pool accumulators)
__global__ void zero_init_kernel(int N, int G) {
    int i = blockIdx.x * blockDim.x + threadIdx.x;
    int stride = gridDim.x * blockDim.x;
    for (int k = i; k < N; k += stride) g_deg[k] = 0;
    for (int k = i; k < G; k += stride) { g_gsum[k] = 0.0f; g_gcnt[k] = 0.0f; }
}

// ---------------------------------------------------------------------------
// 1) decode edges to int32 + degree histogram over dst
// ---------------------------------------------------------------------------
__global__ void prep_kernel(const void* __restrict__ ei, int E, int N) {
    int e = blockIdx.x * blockDim.x + threadIdx.x;
    if (e >= E) return;
    int s = clampi(load_idx(ei, e), 0, N - 1);
    int d = clampi(load_idx(ei, (size_t)E + e), 0, N - 1);
    g_src32[e] = s;
    g_dst32[e] = d;
    atomicAdd(&g_deg[d], 1);
}

// ---------------------------------------------------------------------------
// 2) exclusive scan of deg -> rowptr (3-kernel block scan); cursor = rowptr
// ---------------------------------------------------------------------------
__global__ void scan_blocksum(int N) {
    __shared__ int s[1024];
    int tid = threadIdx.x;
    int i = blockIdx.x * 1024 + tid;
    s[tid] = (i < N) ? g_deg[i] : 0;
    __syncthreads();
#pragma unroll
    for (int o = 512; o; o >>= 1) {
        if (tid < o) s[tid] += s[tid + o];
        __syncthreads();
    }
    if (tid == 0) g_bsum[blockIdx.x] = s[0];
}

__global__ void scan_bsums(int nb) {
    __shared__ int s[1024];
    int tid = threadIdx.x;
    s[tid] = (tid < nb) ? g_bsum[tid] : 0;
    __syncthreads();
#pragma unroll
    for (int o = 1; o < 1024; o <<= 1) {
        int t = (tid >= o) ? s[tid - o] : 0;
        __syncthreads();
        s[tid] += t;
        __syncthreads();
    }
    if (tid < nb) g_bsum[tid] = (tid == 0) ? 0 : s[tid - 1];
}

__global__ void scan_write(int N, int E) {
    __shared__ int s[1024];
    int tid = threadIdx.x;
    int i = blockIdx.x * 1024 + tid;
    int v = (i < N) ? g_deg[i] : 0;
    s[tid] = v;
    __syncthreads();
#pragma unroll
    for (int o = 1; o < 1024; o <<= 1) {
        int t = (tid >= o) ? s[tid - o] : 0;
        __syncthreads();
        s[tid] += t;
        __syncthreads();
    }
    int excl = s[tid] - v + g_bsum[blockIdx.x];
    if (i < N) {
        g_rowptr[i] = excl;
        g_cursor[i] = excl;
        g_dinv[i] = rsqrtf((float)v + 1.0f);
    }
    if (i == N - 1) g_rowptr[N] = E;
}

// ---------------------------------------------------------------------------
// 3) CSR fill by dst: packed {src, norm} entries (reads decoded int32 edges)
// ---------------------------------------------------------------------------
__global__ void fill_kernel(int E) {
    int e = blockIdx.x * blockDim.x + threadIdx.x;
    if (e >= E) return;
    int s = g_src32[e];
    int d = g_dst32[e];
    int pos = atomicAdd(&g_cursor[d], 1);
    if (pos >= 0 && pos < E) {
        float w = g_dinv[s] * g_dinv[d];
        g_csr_ent[pos] = make_int2(s, __float_as_int(w));
    }
}

// ---------------------------------------------------------------------------
// 4) GEMM layer 1:  bufA[n,j] = sum_k x[n,k] * W[k,j]   (K=128, J=32), fp16 out
// ---------------------------------------------------------------------------
__global__ void gemm1_kernel(const float* __restrict__ x, const float* __restrict__ W, int N) {
    __shared__ float Ws[128 * 32];
    __shared__ float Xs[32 * 132];
    int tid = threadIdx.x;  // 128

    for (int i = tid; i < 128 * 32; i += 128) Ws[i] = W[i];

    int n0 = blockIdx.x * 32;
    int rem = N - n0; if (rem > 32) rem = 32;
    for (int idx = tid; idx < rem * 32; idx += 128) {
        int node = idx >> 5, k4 = idx & 31;
        float4 v = *(const float4*)(x + (size_t)(n0 + node) * 128 + k4 * 4);
        float* dp = Xs + node * 132 + 4 * k4;
        dp[0] = v.x; dp[1] = v.y; dp[2] = v.z; dp[3] = v.w;
    }
    __syncthreads();

    int c = tid & 7;   // col group
    int r = tid >> 3;  // node pair
    float acc[2][4];
#pragma unroll
    for (int i = 0; i < 2; i++)
#pragma unroll
        for (int j = 0; j < 4; j++) acc[i][j] = 0.0f;

#pragma unroll 8
    for (int k = 0; k < 128; k++) {
        float4 w = *(const float4*)(Ws + k * 32 + c * 4);
#pragma unroll
        for (int i = 0; i < 2; i++) {
            float xv = Xs[(r * 2 + i) * 132 + k];
            acc[i][0] += xv * w.x;
            acc[i][1] += xv * w.y;
            acc[i][2] += xv * w.z;
            acc[i][3] += xv * w.w;
        }
    }
    uint2* outA = (uint2*)g_bufA;
#pragma unroll
    for (int i = 0; i < 2; i++) {
        int n = n0 + r * 2 + i;
        if (n < N)
            outA[(size_t)n * 8 + c] = pack4h(acc[i][0], acc[i][1], acc[i][2], acc[i][3]);
    }
}

// ---------------------------------------------------------------------------
// 5) GEMM layers 2/3, BN folded into X load:  bufA(fp16) = BN(bufB) @ W
// ---------------------------------------------------------------------------
__global__ void gemm_bn_kernel(const float* __restrict__ W, int N) {
    __shared__ float Ws[32 * 32];
    __shared__ float Xs[64 * 36];
    __shared__ float sc[32], sh[32];
    int tid = threadIdx.x;  // 128

    for (int i = tid; i < 1024; i += 128) Ws[i] = W[i];
    if (tid < 32) { sc[tid] = g_scale[tid]; sh[tid] = g_shift[tid]; }
    __syncthreads();

    int n0 = blockIdx.x * 64;
    for (int idx = tid; idx < 64 * 8; idx += 128) {
        int node = idx >> 3, k4 = idx & 7;
        int n = n0 + node;
        float4 v = (n < N) ? *(const float4*)(g_bufB + (size_t)n * 32 + k4 * 4)
                           : make_float4(0, 0, 0, 0);
        int k = 4 * k4;
        float* dp = Xs + node * 36 + k;
        dp[0] = v.x * sc[k + 0] + sh[k + 0];
        dp[1] = v.y * sc[k + 1] + sh[k + 1];
        dp[2] = v.z * sc[k + 2] + sh[k + 2];
        dp[3] = v.w * sc[k + 3] + sh[k + 3];
    }
    __syncthreads();

    int c = tid & 7, r = tid >> 3;
    float acc[4][4];
#pragma unroll
    for (int i = 0; i < 4; i++)
#pragma unroll
        for (int j = 0; j < 4; j++) acc[i][j] = 0.0f;

#pragma unroll
    for (int k = 0; k < 32; k++) {
        float4 w = *(const float4*)(Ws + k * 32 + c * 4);
#pragma unroll
        for (int i = 0; i < 4; i++) {
            float xv = Xs[(r * 4 + i) * 36 + k];
            acc[i][0] += xv * w.x;
            acc[i][1] += xv * w.y;
            acc[i][2] += xv * w.z;
            acc[i][3] += xv * w.w;
        }
    }
    uint2* outA = (uint2*)g_bufA;
#pragma unroll
    for (int i = 0; i < 4; i++) {
        int n = n0 + r * 4 + i;
        if (n < N)
            outA[(size_t)n * 8 + c] = pack4h(acc[i][0], acc[i][1], acc[i][2], acc[i][3]);
    }
}

// ---------------------------------------------------------------------------
// Paired gather (fp16, pipelined): octets {0,1} -> node vA, octets {2,3} -> vB.
// Two independent rowptr->entry->feature chains per warp. Per node, the two
// oct2 slots cover 16 edges/iter (8 entry regs each, stride 2), with the next
// 16-edge batch prefetched during feature loads. Sentinel {0,0} slots read
// node 0 and add 0. After xor-8 reduce: octet 0 lanes hold vA, octet 2 vB.
// ---------------------------------------------------------------------------
__device__ __forceinline__ float4 gather_pair(const uint2* __restrict__ hs, int vA, int vB, int N) {
    int lane = threadIdx.x & 31;
    int octet = lane >> 3;
    int oct2 = octet & 1;
    int v = (octet >> 1) ? vB : vA;
    bool valid = (v < N);
    int beg = 0, end = 0;
    if (valid) { beg = g_rowptr[v]; end = g_rowptr[v + 1]; }
    float4 acc = make_float4(0.f, 0.f, 0.f, 0.f);
    if (valid && oct2 == 0) {
        float di = g_dinv[v];
        float d2 = di * di;
        uint2 u = hs[(size_t)v * 8];
        float2 f0 = __half22float2(*reinterpret_cast<__half2*>(&u.x));
        float2 f1 = __half22float2(*reinterpret_cast<__half2*>(&u.y));
        acc.x = d2 * f0.x; acc.y = d2 * f0.y; acc.z = d2 * f1.x; acc.w = d2 * f1.y;
    }

    int2 e[8];
#pragma unroll
    for (int j = 0; j < 8; j++) {
        int i = beg + oct2 + 2 * j;
        e[j] = (i < end) ? g_csr_ent[i] : make_int2(0, 0);
    }
    for (int base = beg; base < end; base += 16) {
        int nb = base + 16;
        int2 p[8];
#pragma unroll
        for (int j = 0; j < 8; j++) {
            int i = nb + oct2 + 2 * j;
            p[j] = (i < end) ? g_csr_ent[i] : make_int2(0, 0);
        }
#pragma unroll
        for (int j = 0; j < 8; j++) {
            uint2 u = hs[(size_t)e[j].x * 8];
            float w = __int_as_float(e[j].y);
            float2 f0 = __half22float2(*reinterpret_cast<__half2*>(&u.x));
            float2 f1 = __half22float2(*reinterpret_cast<__half2*>(&u.y));
            acc.x += w * f0.x;
            acc.y += w * f0.y;
            acc.z += w * f1.x;
            acc.w += w * f1.y;
        }
#pragma unroll
        for (int j = 0; j < 8; j++) e[j] = p[j];
    }
    // combine the two oct2 slots of each node (octet 0<->1, octet 2<->3)
    acc.x += __shfl_xor_sync(FULL_MASK, acc.x, 8);
    acc.y += __shfl_xor_sync(FULL_MASK, acc.y, 8);
    acc.z += __shfl_xor_sync(FULL_MASK, acc.z, 8);
    acc.w += __shfl_xor_sync(FULL_MASK, acc.w, 8);
    return acc;
}

// ---------------------------------------------------------------------------
// 6) Gather + tanh + bias + BN partial stats (layers 1, 2). Persistent grid NB2.
// ---------------------------------------------------------------------------
__global__ void gather_stats_kernel(const float* __restrict__ bias, int N) {
    int tid = threadIdx.x, warp = tid >> 5, lane = tid & 31;
    int octet = lane >> 3, sub = lane & 7;
    const uint2* hin = (const uint2*)g_bufA + sub;
    float4* hout = (float4*)g_bufB;
    float4 b4 = ((const float4*)bias)[sub];
    float4 s4 = make_float4(0.f, 0.f, 0.f, 0.f);
    float4 q4 = make_float4(0.f, 0.f, 0.f, 0.f);

    int warpId = blockIdx.x * 8 + warp;
    int nwarp = gridDim.x * 8;
    for (int idx = warpId; 2 * idx < N; idx += nwarp) {
        int vA = 2 * idx, vB = 2 * idx + 1;
        float4 acc = gather_pair(hin, vA, vB, N);
        int v = (octet >> 1) ? vB : vA;
        if ((octet & 1) == 0 && v < N) {
            float4 t;
            t.x = tanhf(acc.x + b4.x);
            t.y = tanhf(acc.y + b4.y);
            t.z = tanhf(acc.z + b4.z);
            t.w = tanhf(acc.w + b4.w);
            hout[(size_t)v * 8 + sub] = t;
            s4.x += t.x; s4.y += t.y; s4.z += t.z; s4.w += t.w;
            q4.x += t.x * t.x; q4.y += t.y * t.y; q4.z += t.z * t.z; q4.w += t.w * t.w;
        }
    }
    // merge octet 2 partials into octet 0
    s4.x += __shfl_xor_sync(FULL_MASK, s4.x, 16);
    s4.y += __shfl_xor_sync(FULL_MASK, s4.y, 16);
    s4.z += __shfl_xor_sync(FULL_MASK, s4.z, 16);
    s4.w += __shfl_xor_sync(FULL_MASK, s4.w, 16);
    q4.x += __shfl_xor_sync(FULL_MASK, q4.x, 16);
    q4.y += __shfl_xor_sync(FULL_MASK, q4.y, 16);
    q4.z += __shfl_xor_sync(FULL_MASK, q4.z, 16);
    q4.w += __shfl_xor_sync(FULL_MASK, q4.w, 16);

    __shared__ float ss[8][32], sq[8][32];
    if (octet == 0) {
        ss[warp][sub * 4 + 0] = s4.x; ss[warp][sub * 4 + 1] = s4.y;
        ss[warp][sub * 4 + 2] = s4.z; ss[warp][sub * 4 + 3] = s4.w;
        sq[warp][sub * 4 + 0] = q4.x; sq[warp][sub * 4 + 1] = q4.y;
        sq[warp][sub * 4 + 2] = q4.z; sq[warp][sub * 4 + 3] = q4.w;
    }
    __syncthreads();
    if (tid < 64) {
        float acc = 0.f;
        if (tid < 32) {
#pragma unroll
            for (int w = 0; w < 8; w++) acc += ss[w][tid];
        } else {
#pragma unroll
            for (int w = 0; w < 8; w++) acc += sq[w][tid - 32];
        }
        g_part[blockIdx.x * 64 + tid] = acc;
    }
}

// deterministic reduce of NB2 partials; scale/shift for folded BN
__global__ void finalize_kernel(const float* __restrict__ g, const float* __restrict__ be,
                                double invN) {
    __shared__ float red[4][64];
    int tid = threadIdx.x;           // 256 threads
    int j = tid & 63, c = tid >> 6;  // feature, chunk
    float acc = 0.f;
    for (int b = c; b < NB2; b += 4) acc += g_part[b * 64 + j];
    red[c][j] = acc;
    __syncthreads();
    if (tid < 32) {
        float S = red[0][tid] + red[1][tid] + red[2][tid] + red[3][tid];
        float Q = red[0][tid + 32] + red[1][tid + 32] + red[2][tid + 32] + red[3][tid + 32];
        float mu  = (float)((double)S * invN);
        float ex2 = (float)((double)Q * invN);
        float var = ex2 - mu * mu;
        float s = g[tid] * rsqrtf(var + 1e-5f);
        g_scale[tid] = s;
        g_shift[tid] = be[tid] - mu * s;
    }
}

// ---------------------------------------------------------------------------
// 7) Gather + tanh + pool head (layer 3): t = tanh(agg + b3) . Wc -> graph sums
// ---------------------------------------------------------------------------
__global__ void gather_pool_kernel(const float* __restrict__ b3, const float* __restrict__ Wc,
                                   const void* __restrict__ batch, int N, int G) {
    int tid = threadIdx.x, warp = tid >> 5, lane = tid & 31;
    int octet = lane >> 3, sub = lane & 7;
    const uint2* hin = (const uint2*)g_bufA + sub;
    float4 b4 = ((const float4*)b3)[sub];
    float4 wc4 = ((const float4*)Wc)[sub];

    int warpId = blockIdx.x * 8 + warp;
    int nwarp = gridDim.x * 8;
    for (int idx = warpId; 2 * idx < N; idx += nwarp) {
        int vA = 2 * idx, vB = 2 * idx + 1;
        float4 acc = gather_pair(hin, vA, vB, N);
        int v = (octet >> 1) ? vB : vA;
        if ((octet & 1) == 0 && v < N) {
            float t = tanhf(acc.x + b4.x) * wc4.x
                    + tanhf(acc.y + b4.y) * wc4.y
                    + tanhf(acc.z + b4.z) * wc4.z
                    + tanhf(acc.w + b4.w) * wc4.w;
            // reduce across the 8 subs of this octet
            unsigned mask = 0xFFu << (octet * 8);
#pragma unroll
            for (int off = 4; off; off >>= 1) t += __shfl_xor_sync(mask, t, off);
            if (sub == 0) {
                int gid = clampi(load_idx(batch, v), 0, G - 1);
                atomicAdd(&g_gsum[gid], t);
                atomicAdd(&g_gcnt[gid], 1.0f);
            }
        }
    }
}

__global__ void out_kernel(const float* __restrict__ bc, float* __restrict__ out, int G) {
    int g = blockIdx.x * blockDim.x + threadIdx.x;
    if (g < G) out[g] = g_gsum[g] / fmaxf(g_gcnt[g], 1.0f) + bc[0];
}

// ---------------------------------------------------------------------------
extern "C" void kernel_launch(void* const* d_in, const int* in_sizes, int n_in,
                              void* d_out, int out_size) {
    const float* x     = (const float*)d_in[0];
    const void*  ei    = d_in[1];
    const void*  batch = d_in[2];
    const float* W1 = (const float*)d_in[3];  const float* b1 = (const float*)d_in[4];
    const float* g1 = (const float*)d_in[5];  const float* be1 = (const float*)d_in[6];
    const float* W2 = (const float*)d_in[7];  const float* b2 = (const float*)d_in[8];
    const float* g2 = (const float*)d_in[9];  const float* be2 = (const float*)d_in[10];
    const float* W3 = (const float*)d_in[11]; const float* b3 = (const float*)d_in[12];
    // d_in[13], d_in[14] (g3/be3) unused: the reference has no BN after layer 3
    const float* Wc = (const float*)d_in[15]; const float* bc = (const float*)d_in[16];
    float* out = (float*)d_out;

    int N = in_sizes[0] / 128;
    int E = in_sizes[1] / 2;
    int G = out_size;

    int eb = (E + 255) / 256;
    int nb = (N + 1023) / 1024;
    int g1Blocks = (N + 31) / 32;
    int gbBlocks = (N + 63) / 64;
    double invN = 1.0 / (double)N;

    // side stream + events for overlapping gemm1 with the CSR build chain.
    static cudaStream_t s2 = 0;
    static cudaEvent_t evFork = 0, evJoin = 0;
    if (!s2) {
        if (cudaStreamCreateWithFlags(&s2, cudaStreamNonBlocking) != cudaSuccess) s2 = 0;
        if (s2) {
            cudaEventCreateWithFlags(&evFork, cudaEventDisableTiming);
            cudaEventCreateWithFlags(&evJoin, cudaEventDisableTiming);
        }
    }

    // ---- init (stream 0) ----
    detect_kernel<<<1, 32>>>((const int*)ei, 2 * E);
    zero_init_kernel<<<256, 256>>>(N, G);

    // ---- fork: gemm1 on s2, CSR build on stream 0 ----
    if (s2) {
        cudaEventRecord(evFork, 0);
        cudaStreamWaitEvent(s2, evFork, 0);
        gemm1_kernel<<<g1Blocks, 128, 0, s2>>>(x, W1, N);
        cudaEventRecord(evJoin, s2);
    } else {
        gemm1_kernel<<<g1Blocks, 128>>>(x, W1, N);
    }

    prep_kernel<<<eb, 256>>>(ei, E, N);
    scan_blocksum<<<nb, 1024>>>(N);
    scan_bsums<<<1, 1024>>>(nb);
    scan_write<<<nb, 1024>>>(N, E);
    fill_kernel<<<eb, 256>>>(E);

    if (s2) cudaStreamWaitEvent(0, evJoin, 0);

    // ---- layer 1 ----
    gather_stats_kernel<<<NB2, 256>>>(b1, N);
    finalize_kernel<<<1, 256>>>(g1, be1, invN);

    // ---- layer 2 ----
    gemm_bn_kernel<<<gbBlocks, 128>>>(W2, N);
    gather_stats_kernel<<<NB2, 256>>>(b2, N);
    finalize_kernel<<<1, 256>>>(g2, be2, invN);

    // ---- layer 3 ----
    gemm_bn_kernel<<<gbBlocks, 128>>>(W3, N);
    gather_pool_kernel<<<NB2, 256>>>(b3, Wc, batch, N, G);

    // ---- head ----
    out_kernel<<<(G + 255) / 256, 256>>>(bc, out, G);
}

// round 17
// speedup vs baseline: 1.3454x; 1.1709x over previous
#include <cuda_runtime.h>
#include <cuda_fp16.h>
#include <math.h>

#define FULL_MASK 0xFFFFFFFFu

#define MAXN 200000
#define MAXE 6400000
#define MAXG 4096
#define NBG 592      // persistent gather blocks = 4/SM x 148 SMs

// ---- scratch: static device globals, referenced DIRECTLY by kernels ----
__device__ __align__(16) int    g_deg[MAXN];
__device__ __align__(16) int    g_rowptr[MAXN + 1];
__device__ __align__(16) int    g_cursor[MAXN];
__device__ __align__(16) int    g_bsum[1024];
__device__ __align__(16) int    g_src32[MAXE];
__device__ __align__(16) int    g_dst32[MAXE];
__device__ __align__(16) int2   g_csr_ent[MAXE];      // {src, norm bits}
__device__ __align__(16) float  g_dinv[MAXN];
__device__ __align__(16) __half g_bufA[MAXN * 32];    // fp16 gather input
__device__ __align__(16) float  g_bufB[MAXN * 32];    // fp32 gather output
__device__ __align__(16) float  g_part[NBG * 64];     // per-block [sum(32)|sumsq(32)]
__device__ __align__(16) float  g_scale[32];
__device__ __align__(16) float  g_shift[32];
__device__ __align__(16) float  g_gsum[MAXG];
__device__ __align__(16) float  g_gcnt[MAXG];
__device__ int g_is64;   // 1 if integer inputs are int64 on device, else int32

__device__ __forceinline__ int load_idx(const void* p, size_t i) {
    if (g_is64) return (int)(((const long long*)p)[i]);
    return ((const int*)p)[i];
}
__device__ __forceinline__ int clampi(int v, int lo, int hi) {
    return v < lo ? lo : (v > hi ? hi : v);
}
__device__ __forceinline__ uint2 pack4h(float a, float b, float c, float d) {
    __half2 h0 = __float22half2_rn(make_float2(a, b));
    __half2 h1 = __float22half2_rn(make_float2(c, d));
    uint2 u;
    u.x = *reinterpret_cast<unsigned*>(&h0);
    u.y = *reinterpret_cast<unsigned*>(&h1);
    return u;
}

// ---------------------------------------------------------------------------
// 0a) dtype detection: int64 values < 2^31 have zero odd 32-bit words.
// ---------------------------------------------------------------------------
__global__ void detect_kernel(const int* __restrict__ ei_words, int nwords) {
    if (threadIdx.x == 0 && blockIdx.x == 0) {
        int acc = 0;
        for (int i = 1; i < 32 && i < nwords; i += 2) acc |= ei_words[i];
        g_is64 = (acc == 0) ? 1 : 0;
    }
}

// 0b) zero init (deg histogram + pool accumulators)
__global__ void zero_init_kernel(int N, int G) {
    int i = blockIdx.x * blockDim.x + threadIdx.x;
    int stride = gridDim.x * blockDim.x;
    for (int k = i; k < N; k += stride) g_deg[k] = 0;
    for (int k = i; k < G; k += stride) { g_gsum[k] = 0.0f; g_gcnt[k] = 0.0f; }
}

// ---------------------------------------------------------------------------
// 1) decode edges to int32 + degree histogram over dst
// ---------------------------------------------------------------------------
__global__ void prep_kernel(const void* __restrict__ ei, int E, int N) {
    int e = blockIdx.x * blockDim.x + threadIdx.x;
    if (e >= E) return;
    int s = clampi(load_idx(ei, e), 0, N - 1);
    int d = clampi(load_idx(ei, (size_t)E + e), 0, N - 1);
    g_src32[e] = s;
    g_dst32[e] = d;
    atomicAdd(&g_deg[d], 1);
}

// ---------------------------------------------------------------------------
// 2) exclusive scan of deg -> rowptr (3-kernel block scan); cursor = rowptr
// ---------------------------------------------------------------------------
__global__ void scan_blocksum(int N) {
    __shared__ int s[1024];
    int tid = threadIdx.x;
    int i = blockIdx.x * 1024 + tid;
    s[tid] = (i < N) ? g_deg[i] : 0;
    __syncthreads();
#pragma unroll
    for (int o = 512; o; o >>= 1) {
        if (tid < o) s[tid] += s[tid + o];
        __syncthreads();
    }
    if (tid == 0) g_bsum[blockIdx.x] = s[0];
}

__global__ void scan_bsums(int nb) {
    __shared__ int s[1024];
    int tid = threadIdx.x;
    s[tid] = (tid < nb) ? g_bsum[tid] : 0;
    __syncthreads();
#pragma unroll
    for (int o = 1; o < 1024; o <<= 1) {
        int t = (tid >= o) ? s[tid - o] : 0;
        __syncthreads();
        s[tid] += t;
        __syncthreads();
    }
    if (tid < nb) g_bsum[tid] = (tid == 0) ? 0 : s[tid - 1];
}

__global__ void scan_write(int N, int E) {
    __shared__ int s[1024];
    int tid = threadIdx.x;
    int i = blockIdx.x * 1024 + tid;
    int v = (i < N) ? g_deg[i] : 0;
    s[tid] = v;
    __syncthreads();
#pragma unroll
    for (int o = 1; o < 1024; o <<= 1) {
        int t = (tid >= o) ? s[tid - o] : 0;
        __syncthreads();
        s[tid] += t;
        __syncthreads();
    }
    int excl = s[tid] - v + g_bsum[blockIdx.x];
    if (i < N) {
        g_rowptr[i] = excl;
        g_cursor[i] = excl;
        g_dinv[i] = rsqrtf((float)v + 1.0f);
    }
    if (i == N - 1) g_rowptr[N] = E;
}

// ---------------------------------------------------------------------------
// 3) CSR fill by dst: packed {src, norm} entries (reads decoded int32 edges)
// ---------------------------------------------------------------------------
__global__ void fill_kernel(int E) {
    int e = blockIdx.x * blockDim.x + threadIdx.x;
    if (e >= E) return;
    int s = g_src32[e];
    int d = g_dst32[e];
    int pos = atomicAdd(&g_cursor[d], 1);
    if (pos >= 0 && pos < E) {
        float w = g_dinv[s] * g_dinv[d];
        g_csr_ent[pos] = make_int2(s, __float_as_int(w));
    }
}

// ---------------------------------------------------------------------------
// 4) GEMM layer 1:  bufA[n,j] = sum_k x[n,k] * W[k,j]   (K=128, J=32), fp16 out
// ---------------------------------------------------------------------------
__global__ void gemm1_kernel(const float* __restrict__ x, const float* __restrict__ W, int N) {
    __shared__ float Ws[128 * 32];
    __shared__ float Xs[32 * 132];
    int tid = threadIdx.x;  // 128

    for (int i = tid; i < 128 * 32; i += 128) Ws[i] = W[i];

    int n0 = blockIdx.x * 32;
    int rem = N - n0; if (rem > 32) rem = 32;
    for (int idx = tid; idx < rem * 32; idx += 128) {
        int node = idx >> 5, k4 = idx & 31;
        float4 v = *(const float4*)(x + (size_t)(n0 + node) * 128 + k4 * 4);
        float* dp = Xs + node * 132 + 4 * k4;
        dp[0] = v.x; dp[1] = v.y; dp[2] = v.z; dp[3] = v.w;
    }
    __syncthreads();

    int c = tid & 7;   // col group
    int r = tid >> 3;  // node pair
    float acc[2][4];
#pragma unroll
    for (int i = 0; i < 2; i++)
#pragma unroll
        for (int j = 0; j < 4; j++) acc[i][j] = 0.0f;

#pragma unroll 8
    for (int k = 0; k < 128; k++) {
        float4 w = *(const float4*)(Ws + k * 32 + c * 4);
#pragma unroll
        for (int i = 0; i < 2; i++) {
            float xv = Xs[(r * 2 + i) * 132 + k];
            acc[i][0] += xv * w.x;
            acc[i][1] += xv * w.y;
            acc[i][2] += xv * w.z;
            acc[i][3] += xv * w.w;
        }
    }
    uint2* outA = (uint2*)g_bufA;
#pragma unroll
    for (int i = 0; i < 2; i++) {
        int n = n0 + r * 2 + i;
        if (n < N)
            outA[(size_t)n * 8 + c] = pack4h(acc[i][0], acc[i][1], acc[i][2], acc[i][3]);
    }
}

// ---------------------------------------------------------------------------
// 5) GEMM layers 2/3, BN folded into X load:  bufA(fp16) = BN(bufB) @ W
// ---------------------------------------------------------------------------
__global__ void gemm_bn_kernel(const float* __restrict__ W, int N) {
    __shared__ float Ws[32 * 32];
    __shared__ float Xs[64 * 36];
    __shared__ float sc[32], sh[32];
    int tid = threadIdx.x;  // 128

    for (int i = tid; i < 1024; i += 128) Ws[i] = W[i];
    if (tid < 32) { sc[tid] = g_scale[tid]; sh[tid] = g_shift[tid]; }
    __syncthreads();

    int n0 = blockIdx.x * 64;
    for (int idx = tid; idx < 64 * 8; idx += 128) {
        int node = idx >> 3, k4 = idx & 7;
        int n = n0 + node;
        float4 v = (n < N) ? *(const float4*)(g_bufB + (size_t)n * 32 + k4 * 4)
                           : make_float4(0, 0, 0, 0);
        int k = 4 * k4;
        float* dp = Xs + node * 36 + k;
        dp[0] = v.x * sc[k + 0] + sh[k + 0];
        dp[1] = v.y * sc[k + 1] + sh[k + 1];
        dp[2] = v.z * sc[k + 2] + sh[k + 2];
        dp[3] = v.w * sc[k + 3] + sh[k + 3];
    }
    __syncthreads();

    int c = tid & 7, r = tid >> 3;
    float acc[4][4];
#pragma unroll
    for (int i = 0; i < 4; i++)
#pragma unroll
        for (int j = 0; j < 4; j++) acc[i][j] = 0.0f;

#pragma unroll
    for (int k = 0; k < 32; k++) {
        float4 w = *(const float4*)(Ws + k * 32 + c * 4);
#pragma unroll
        for (int i = 0; i < 4; i++) {
            float xv = Xs[(r * 4 + i) * 36 + k];
            acc[i][0] += xv * w.x;
            acc[i][1] += xv * w.y;
            acc[i][2] += xv * w.z;
            acc[i][3] += xv * w.w;
        }
    }
    uint2* outA = (uint2*)g_bufA;
#pragma unroll
    for (int i = 0; i < 4; i++) {
        int n = n0 + r * 4 + i;
        if (n < N)
            outA[(size_t)n * 8 + c] = pack4h(acc[i][0], acc[i][1], acc[i][2], acc[i][3]);
    }
}

// ---------------------------------------------------------------------------
// Paired gather (fp16, pipelined, reg-lean): octets {0,1} -> node vA,
// {2,3} -> vB. Per node the two oct2 slots cover 8 edges/iter via e[4]/p[4]
// double-buffered entries (4 feature + 4 prefetch LDGs in flight per lane).
// Sentinel {0,0} slots read node 0 and add 0. After xor-8: octet 0 = vA,
// octet 2 = vB.
// ---------------------------------------------------------------------------
__device__ __forceinline__ float4 gather_pair(const uint2* __restrict__ hs, int vA, int vB, int N) {
    int lane = threadIdx.x & 31;
    int octet = lane >> 3;
    int oct2 = octet & 1;
    int v = (octet >> 1) ? vB : vA;
    bool valid = (v < N);
    int beg = 0, end = 0;
    if (valid) { beg = g_rowptr[v]; end = g_rowptr[v + 1]; }
    float4 acc = make_float4(0.f, 0.f, 0.f, 0.f);
    if (valid && oct2 == 0) {
        float di = g_dinv[v];
        float d2 = di * di;
        uint2 u = hs[(size_t)v * 8];
        float2 f0 = __half22float2(*reinterpret_cast<__half2*>(&u.x));
        float2 f1 = __half22float2(*reinterpret_cast<__half2*>(&u.y));
        acc.x = d2 * f0.x; acc.y = d2 * f0.y; acc.z = d2 * f1.x; acc.w = d2 * f1.y;
    }

    int2 e[4];
#pragma unroll
    for (int j = 0; j < 4; j++) {
        int i = beg + oct2 + 2 * j;
        e[j] = (i < end) ? g_csr_ent[i] : make_int2(0, 0);
    }
    for (int base = beg; base < end; base += 8) {
        int nb = base + 8;
        int2 p[4];
#pragma unroll
        for (int j = 0; j < 4; j++) {
            int i = nb + oct2 + 2 * j;
            p[j] = (i < end) ? g_csr_ent[i] : make_int2(0, 0);
        }
#pragma unroll
        for (int j = 0; j < 4; j++) {
            uint2 u = hs[(size_t)e[j].x * 8];
            float w = __int_as_float(e[j].y);
            float2 f0 = __half22float2(*reinterpret_cast<__half2*>(&u.x));
            float2 f1 = __half22float2(*reinterpret_cast<__half2*>(&u.y));
            acc.x += w * f0.x;
            acc.y += w * f0.y;
            acc.z += w * f1.x;
            acc.w += w * f1.y;
        }
#pragma unroll
        for (int j = 0; j < 4; j++) e[j] = p[j];
    }
    // combine the two oct2 slots of each node (octet 0<->1, octet 2<->3)
    acc.x += __shfl_xor_sync(FULL_MASK, acc.x, 8);
    acc.y += __shfl_xor_sync(FULL_MASK, acc.y, 8);
    acc.z += __shfl_xor_sync(FULL_MASK, acc.z, 8);
    acc.w += __shfl_xor_sync(FULL_MASK, acc.w, 8);
    return acc;
}

// ---------------------------------------------------------------------------
// 6) Gather + tanh + bias + BN partial stats (layers 1, 2). Persistent NBG grid.
// ---------------------------------------------------------------------------
__global__ void __launch_bounds__(256, 4)
gather_stats_kernel(const float* __restrict__ bias, int N) {
    int tid = threadIdx.x, warp = tid >> 5, lane = tid & 31;
    int octet = lane >> 3, sub = lane & 7;
    const uint2* hin = (const uint2*)g_bufA + sub;
    float4* hout = (float4*)g_bufB;
    float4 b4 = ((const float4*)bias)[sub];
    float4 s4 = make_float4(0.f, 0.f, 0.f, 0.f);
    float4 q4 = make_float4(0.f, 0.f, 0.f, 0.f);

    int warpId = blockIdx.x * 8 + warp;
    int nwarp = gridDim.x * 8;
    for (int idx = warpId; 2 * idx < N; idx += nwarp) {
        int vA = 2 * idx, vB = 2 * idx + 1;
        float4 acc = gather_pair(hin, vA, vB, N);
        int v = (octet >> 1) ? vB : vA;
        if ((octet & 1) == 0 && v < N) {
            float4 t;
            t.x = tanhf(acc.x + b4.x);
            t.y = tanhf(acc.y + b4.y);
            t.z = tanhf(acc.z + b4.z);
            t.w = tanhf(acc.w + b4.w);
            hout[(size_t)v * 8 + sub] = t;
            s4.x += t.x; s4.y += t.y; s4.z += t.z; s4.w += t.w;
            q4.x += t.x * t.x; q4.y += t.y * t.y; q4.z += t.z * t.z; q4.w += t.w * t.w;
        }
    }
    // merge octet 2 partials into octet 0
    s4.x += __shfl_xor_sync(FULL_MASK, s4.x, 16);
    s4.y += __shfl_xor_sync(FULL_MASK, s4.y, 16);
    s4.z += __shfl_xor_sync(FULL_MASK, s4.z, 16);
    s4.w += __shfl_xor_sync(FULL_MASK, s4.w, 16);
    q4.x += __shfl_xor_sync(FULL_MASK, q4.x, 16);
    q4.y += __shfl_xor_sync(FULL_MASK, q4.y, 16);
    q4.z += __shfl_xor_sync(FULL_MASK, q4.z, 16);
    q4.w += __shfl_xor_sync(FULL_MASK, q4.w, 16);

    __shared__ float ss[8][32], sq[8][32];
    if (octet == 0) {
        ss[warp][sub * 4 + 0] = s4.x; ss[warp][sub * 4 + 1] = s4.y;
        ss[warp][sub * 4 + 2] = s4.z; ss[warp][sub * 4 + 3] = s4.w;
        sq[warp][sub * 4 + 0] = q4.x; sq[warp][sub * 4 + 1] = q4.y;
        sq[warp][sub * 4 + 2] = q4.z; sq[warp][sub * 4 + 3] = q4.w;
    }
    __syncthreads();
    if (tid < 64) {
        float acc = 0.f;
        if (tid < 32) {
#pragma unroll
            for (int w = 0; w < 8; w++) acc += ss[w][tid];
        } else {
#pragma unroll
            for (int w = 0; w < 8; w++) acc += sq[w][tid - 32];
        }
        g_part[blockIdx.x * 64 + tid] = acc;
    }
}

// deterministic reduce of NBG partials; scale/shift for folded BN
__global__ void finalize_kernel(const float* __restrict__ g, const float* __restrict__ be,
                                double invN) {
    __shared__ float red[4][64];
    int tid = threadIdx.x;           // 256 threads
    int j = tid & 63, c = tid >> 6;  // feature, chunk
    float acc = 0.f;
    for (int b = c; b < NBG; b += 4) acc += g_part[b * 64 + j];
    red[c][j] = acc;
    __syncthreads();
    if (tid < 32) {
        float S = red[0][tid] + red[1][tid] + red[2][tid] + red[3][tid];
        float Q = red[0][tid + 32] + red[1][tid + 32] + red[2][tid + 32] + red[3][tid + 32];
        float mu  = (float)((double)S * invN);
        float ex2 = (float)((double)Q * invN);
        float var = ex2 - mu * mu;
        float s = g[tid] * rsqrtf(var + 1e-5f);
        g_scale[tid] = s;
        g_shift[tid] = be[tid] - mu * s;
    }
}

// ---------------------------------------------------------------------------
// 7) Gather + tanh + pool head (layer 3): t = tanh(agg + b3) . Wc -> graph sums
// ---------------------------------------------------------------------------
__global__ void __launch_bounds__(256, 4)
gather_pool_kernel(const float* __restrict__ b3, const float* __restrict__ Wc,
                   const void* __restrict__ batch, int N, int G) {
    int tid = threadIdx.x, warp = tid >> 5, lane = tid & 31;
    int octet = lane >> 3, sub = lane & 7;
    const uint2* hin = (const uint2*)g_bufA + sub;
    float4 b4 = ((const float4*)b3)[sub];
    float4 wc4 = ((const float4*)Wc)[sub];

    int warpId = blockIdx.x * 8 + warp;
    int nwarp = gridDim.x * 8;
    for (int idx = warpId; 2 * idx < N; idx += nwarp) {
        int vA = 2 * idx, vB = 2 * idx + 1;
        float4 acc = gather_pair(hin, vA, vB, N);
        int v = (octet >> 1) ? vB : vA;
        if ((octet & 1) == 0 && v < N) {
            float t = tanhf(acc.x + b4.x) * wc4.x
                    + tanhf(acc.y + b4.y) * wc4.y
                    + tanhf(acc.z + b4.z) * wc4.z
                    + tanhf(acc.w + b4.w) * wc4.w;
            // reduce across the 8 subs of this octet
            unsigned mask = 0xFFu << (octet * 8);
#pragma unroll
            for (int off = 4; off; off >>= 1) t += __shfl_xor_sync(mask, t, off);
            if (sub == 0) {
                int gid = clampi(load_idx(batch, v), 0, G - 1);
                atomicAdd(&g_gsum[gid], t);
                atomicAdd(&g_gcnt[gid], 1.0f);
            }
        }
    }
}

__global__ void out_kernel(const float* __restrict__ bc, float* __restrict__ out, int G) {
    int g = blockIdx.x * blockDim.x + threadIdx.x;
    if (g < G) out[g] = g_gsum[g] / fmaxf(g_gcnt[g], 1.0f) + bc[0];
}

// ---------------------------------------------------------------------------
extern "C" void kernel_launch(void* const* d_in, const int* in_sizes, int n_in,
                              void* d_out, int out_size) {
    const float* x     = (const float*)d_in[0];
    const void*  ei    = d_in[1];
    const void*  batch = d_in[2];
    const float* W1 = (const float*)d_in[3];  const float* b1 = (const float*)d_in[4];
    const float* g1 = (const float*)d_in[5];  const float* be1 = (const float*)d_in[6];
    const float* W2 = (const float*)d_in[7];  const float* b2 = (const float*)d_in[8];
    const float* g2 = (const float*)d_in[9];  const float* be2 = (const float*)d_in[10];
    const float* W3 = (const float*)d_in[11]; const float* b3 = (const float*)d_in[12];
    // d_in[13], d_in[14] (g3/be3) unused: the reference has no BN after layer 3
    const float* Wc = (const float*)d_in[15]; const float* bc = (const float*)d_in[16];
    float* out = (float*)d_out;

    int N = in_sizes[0] / 128;
    int E = in_sizes[1] / 2;
    int G = out_size;

    int eb = (E + 255) / 256;
    int nb = (N + 1023) / 1024;
    int g1Blocks = (N + 31) / 32;
    int gbBlocks = (N + 63) / 64;
    double invN = 1.0 / (double)N;

    // side stream + events for overlapping gemm1 with the CSR build chain.
    static cudaStream_t s2 = 0;
    static cudaEvent_t evFork = 0, evJoin = 0;
    if (!s2) {
        if (cudaStreamCreateWithFlags(&s2, cudaStreamNonBlocking) != cudaSuccess) s2 = 0;
        if (s2) {
            cudaEventCreateWithFlags(&evFork, cudaEventDisableTiming);
            cudaEventCreateWithFlags(&evJoin, cudaEventDisableTiming);
        }
    }

    // ---- init (stream 0) ----
    detect_kernel<<<1, 32>>>((const int*)ei, 2 * E);
    zero_init_kernel<<<256, 256>>>(N, G);

    // ---- fork: gemm1 on s2, CSR build on stream 0 ----
    if (s2) {
        cudaEventRecord(evFork, 0);
        cudaStreamWaitEvent(s2, evFork, 0);
        gemm1_kernel<<<g1Blocks, 128, 0, s2>>>(x, W1, N);
        cudaEventRecord(evJoin, s2);
    } else {
        gemm1_kernel<<<g1Blocks, 128>>>(x, W1, N);
    }

    prep_kernel<<<eb, 256>>>(ei, E, N);
    scan_blocksum<<<nb, 1024>>>(N);
    scan_bsums<<<1, 1024>>>(nb);
    scan_write<<<nb, 1024>>>(N, E);
    fill_kernel<<<eb, 256>>>(E);

    if (s2) cudaStreamWaitEvent(0, evJoin, 0);

    // ---- layer 1 ----
    gather_stats_kernel<<<NBG, 256>>>(b1, N);
    finalize_kernel<<<1, 256>>>(g1, be1, invN);

    // ---- layer 2 ----
    gemm_bn_kernel<<<gbBlocks, 128>>>(W2, N);
    gather_stats_kernel<<<NBG, 256>>>(b2, N);
    finalize_kernel<<<1, 256>>>(g2, be2, invN);

    // ---- layer 3 ----
    gemm_bn_kernel<<<gbBlocks, 128>>>(W3, N);
    gather_pool_kernel<<<NBG, 256>>>(b3, Wc, batch, N, G);

    // ---- head ----
    out_kernel<<<(G + 255) / 256, 256>>>(bc, out, G);
}